// round 1
// baseline (speedup 1.0000x reference)
#include <cuda_runtime.h>
#include <cstddef>

// Problem constants (fixed shapes)
#define HIDC   512
#define NTOK   1024
#define BATCH  32
#define CEFF   1280

// ---------------------------------------------------------------------------
// Scratch (no allocations allowed -> __device__ globals)
// ---------------------------------------------------------------------------
__device__ float g_Wqc[HIDC * HIDC];          // W_q @ W_cnn        [512,512]
__device__ float g_Wke[HIDC * CEFF];          // W_k @ W_eff        [512,1280]
__device__ float g_Wve[HIDC * CEFF];          // W_v @ W_eff        [512,1280]
__device__ float g_bqc[HIDC];
__device__ float g_bke[HIDC];
__device__ float g_bve[HIDC];
__device__ float g_q[(size_t)BATCH * HIDC * NTOK];     // [b][c][n]
__device__ float g_k[(size_t)BATCH * HIDC * NTOK];     // [b][c][n]
__device__ float g_v[(size_t)BATCH * HIDC * NTOK];     // [b][c][n]
__device__ float g_attn[(size_t)BATCH * NTOK * NTOK];  // [b][n][m]

// ---------------------------------------------------------------------------
// Generic NN SGEMM:  C[b][m][n] = sum_k A[m][k] * B[b][k][n] (+ bias[m])
// A row-major [M,K] (weights, unbatched), B row-major [K,N] batched.
// BM=BN=128, BK=8, 256 threads, 8x8 per-thread microtile.
// All dims assumed multiples of tile sizes (true for this problem).
// ---------------------------------------------------------------------------
__global__ __launch_bounds__(256) void sgemm_nn(
    const float* __restrict__ A, int lda,
    const float* __restrict__ B, int ldb, size_t sB,
    float* __restrict__ C, int ldc, size_t sC,
    const float* __restrict__ bias, int K)
{
    __shared__ float As[8][128];
    __shared__ float Bs[8][128];

    const int tid = threadIdx.x;
    const int bx = blockIdx.x, by = blockIdx.y, bz = blockIdx.z;

    const float* Ab = A + (size_t)by * 128 * lda;
    const float* Bb = B + (size_t)bz * sB + (size_t)bx * 128;
    float*       Cb = C + (size_t)bz * sC + (size_t)by * 128 * ldc + (size_t)bx * 128;

    // A tile load: 128 rows x 8 k, one float4 per thread, transpose into As
    const int a_r = tid >> 1;            // 0..127
    const int a_c = (tid & 1) * 4;       // 0 or 4
    // B tile load: 8 k rows x 128 n, one float4 per thread
    const int b_r = tid >> 5;            // 0..7
    const int b_c = (tid & 31) * 4;      // 0..124

    const int tx = tid & 15;             // n fragment
    const int ty = tid >> 4;             // m fragment

    float acc[8][8];
    #pragma unroll
    for (int i = 0; i < 8; i++)
        #pragma unroll
        for (int j = 0; j < 8; j++) acc[i][j] = 0.f;

    for (int k0 = 0; k0 < K; k0 += 8) {
        float4 av = *(const float4*)(Ab + (size_t)a_r * lda + k0 + a_c);
        As[a_c + 0][a_r] = av.x;
        As[a_c + 1][a_r] = av.y;
        As[a_c + 2][a_r] = av.z;
        As[a_c + 3][a_r] = av.w;
        *(float4*)(&Bs[b_r][b_c]) = *(const float4*)(Bb + (size_t)(k0 + b_r) * ldb + b_c);
        __syncthreads();

        #pragma unroll
        for (int k = 0; k < 8; k++) {
            float4 a0 = *(const float4*)(&As[k][ty * 8]);
            float4 a1 = *(const float4*)(&As[k][ty * 8 + 4]);
            float4 b0 = *(const float4*)(&Bs[k][tx * 8]);
            float4 b1 = *(const float4*)(&Bs[k][tx * 8 + 4]);
            float ra[8] = {a0.x, a0.y, a0.z, a0.w, a1.x, a1.y, a1.z, a1.w};
            float rb[8] = {b0.x, b0.y, b0.z, b0.w, b1.x, b1.y, b1.z, b1.w};
            #pragma unroll
            for (int i = 0; i < 8; i++)
                #pragma unroll
                for (int j = 0; j < 8; j++)
                    acc[i][j] += ra[i] * rb[j];
        }
        __syncthreads();
    }

    #pragma unroll
    for (int i = 0; i < 8; i++) {
        float bv = bias ? bias[by * 128 + ty * 8 + i] : 0.f;
        float* cr = Cb + (size_t)(ty * 8 + i) * ldc + tx * 8;
        float4 o0, o1;
        o0.x = acc[i][0] + bv; o0.y = acc[i][1] + bv;
        o0.z = acc[i][2] + bv; o0.w = acc[i][3] + bv;
        o1.x = acc[i][4] + bv; o1.y = acc[i][5] + bv;
        o1.z = acc[i][6] + bv; o1.w = acc[i][7] + bv;
        *(float4*)(cr)     = o0;
        *(float4*)(cr + 4) = o1;
    }
}

// ---------------------------------------------------------------------------
// TN SGEMM (attention logits): C[b][n][m] = sum_c Q[b][c][n] * Kt[b][c][m]
// Both operands K-major [C,N] with ld = 1024. Fixed sizes M=N=1024, K=512.
// ---------------------------------------------------------------------------
__global__ __launch_bounds__(256) void sgemm_tn_logits(
    const float* __restrict__ Q, const float* __restrict__ Kt,
    float* __restrict__ C)
{
    __shared__ float As[8][128];
    __shared__ float Bs[8][128];

    const int tid = threadIdx.x;
    const float* Ab = Q  + (size_t)blockIdx.z * (HIDC * NTOK) + (size_t)blockIdx.y * 128;
    const float* Bb = Kt + (size_t)blockIdx.z * (HIDC * NTOK) + (size_t)blockIdx.x * 128;
    float*       Cb = C  + (size_t)blockIdx.z * (NTOK * NTOK)
                         + (size_t)blockIdx.y * 128 * NTOK + (size_t)blockIdx.x * 128;

    const int l_r = tid >> 5;            // 0..7
    const int l_c = (tid & 31) * 4;      // 0..124
    const int tx = tid & 15;
    const int ty = tid >> 4;

    float acc[8][8];
    #pragma unroll
    for (int i = 0; i < 8; i++)
        #pragma unroll
        for (int j = 0; j < 8; j++) acc[i][j] = 0.f;

    for (int k0 = 0; k0 < HIDC; k0 += 8) {
        *(float4*)(&As[l_r][l_c]) = *(const float4*)(Ab + (size_t)(k0 + l_r) * NTOK + l_c);
        *(float4*)(&Bs[l_r][l_c]) = *(const float4*)(Bb + (size_t)(k0 + l_r) * NTOK + l_c);
        __syncthreads();

        #pragma unroll
        for (int k = 0; k < 8; k++) {
            float4 a0 = *(const float4*)(&As[k][ty * 8]);
            float4 a1 = *(const float4*)(&As[k][ty * 8 + 4]);
            float4 b0 = *(const float4*)(&Bs[k][tx * 8]);
            float4 b1 = *(const float4*)(&Bs[k][tx * 8 + 4]);
            float ra[8] = {a0.x, a0.y, a0.z, a0.w, a1.x, a1.y, a1.z, a1.w};
            float rb[8] = {b0.x, b0.y, b0.z, b0.w, b1.x, b1.y, b1.z, b1.w};
            #pragma unroll
            for (int i = 0; i < 8; i++)
                #pragma unroll
                for (int j = 0; j < 8; j++)
                    acc[i][j] += ra[i] * rb[j];
        }
        __syncthreads();
    }

    #pragma unroll
    for (int i = 0; i < 8; i++) {
        float* cr = Cb + (size_t)(ty * 8 + i) * NTOK + tx * 8;
        *(float4*)(cr)     = make_float4(acc[i][0], acc[i][1], acc[i][2], acc[i][3]);
        *(float4*)(cr + 4) = make_float4(acc[i][4], acc[i][5], acc[i][6], acc[i][7]);
    }
}

// ---------------------------------------------------------------------------
// NT SGEMM + epilogue: out[b][c][n] = gamma * sum_m V[b][c][m]*attn[b][n][m]
//                                     + out[b][c][n]   (cnn_proj residual)
// A = V [C=512, M=1024] m-contig; B = attn [N=1024, M=1024] m-contig.
// Fixed: Mdim(c)=512, Ndim(n)=1024, K(m)=1024.
// ---------------------------------------------------------------------------
__global__ __launch_bounds__(256) void sgemm_nt_out(
    const float* __restrict__ V, const float* __restrict__ Attn,
    float* __restrict__ Out, const float* __restrict__ gamma)
{
    __shared__ float As[8][128];
    __shared__ float Bs[8][128];

    const int tid = threadIdx.x;
    const float* Ab = V    + (size_t)blockIdx.z * (HIDC * NTOK) + (size_t)blockIdx.y * 128 * NTOK;
    const float* Bb = Attn + (size_t)blockIdx.z * (NTOK * NTOK) + (size_t)blockIdx.x * 128 * NTOK;
    float*       Cb = Out  + (size_t)blockIdx.z * (HIDC * NTOK)
                           + (size_t)blockIdx.y * 128 * NTOK + (size_t)blockIdx.x * 128;

    const int a_r = tid >> 1;           // 0..127 (row within tile)
    const int a_c = (tid & 1) * 4;      // 0 or 4 (k offset)
    const int tx = tid & 15;
    const int ty = tid >> 4;

    float acc[8][8];
    #pragma unroll
    for (int i = 0; i < 8; i++)
        #pragma unroll
        for (int j = 0; j < 8; j++) acc[i][j] = 0.f;

    for (int k0 = 0; k0 < NTOK; k0 += 8) {
        float4 av = *(const float4*)(Ab + (size_t)a_r * NTOK + k0 + a_c);
        As[a_c + 0][a_r] = av.x;
        As[a_c + 1][a_r] = av.y;
        As[a_c + 2][a_r] = av.z;
        As[a_c + 3][a_r] = av.w;
        float4 bv = *(const float4*)(Bb + (size_t)a_r * NTOK + k0 + a_c);
        Bs[a_c + 0][a_r] = bv.x;
        Bs[a_c + 1][a_r] = bv.y;
        Bs[a_c + 2][a_r] = bv.z;
        Bs[a_c + 3][a_r] = bv.w;
        __syncthreads();

        #pragma unroll
        for (int k = 0; k < 8; k++) {
            float4 a0 = *(const float4*)(&As[k][ty * 8]);
            float4 a1 = *(const float4*)(&As[k][ty * 8 + 4]);
            float4 b0 = *(const float4*)(&Bs[k][tx * 8]);
            float4 b1 = *(const float4*)(&Bs[k][tx * 8 + 4]);
            float ra[8] = {a0.x, a0.y, a0.z, a0.w, a1.x, a1.y, a1.z, a1.w};
            float rb[8] = {b0.x, b0.y, b0.z, b0.w, b1.x, b1.y, b1.z, b1.w};
            #pragma unroll
            for (int i = 0; i < 8; i++)
                #pragma unroll
                for (int j = 0; j < 8; j++)
                    acc[i][j] += ra[i] * rb[j];
        }
        __syncthreads();
    }

    const float g = gamma[0];
    #pragma unroll
    for (int i = 0; i < 8; i++) {
        float* cr = Cb + (size_t)(ty * 8 + i) * NTOK + tx * 8;
        float4 c0 = *(const float4*)(cr);
        float4 c1 = *(const float4*)(cr + 4);
        c0.x = g * acc[i][0] + c0.x; c0.y = g * acc[i][1] + c0.y;
        c0.z = g * acc[i][2] + c0.z; c0.w = g * acc[i][3] + c0.w;
        c1.x = g * acc[i][4] + c1.x; c1.y = g * acc[i][5] + c1.y;
        c1.z = g * acc[i][6] + c1.z; c1.w = g * acc[i][7] + c1.w;
        *(float4*)(cr)     = c0;
        *(float4*)(cr + 4) = c1;
    }
}

// ---------------------------------------------------------------------------
// Row softmax over attn [B*N rows, N cols]. One block of 256 threads per row.
// ---------------------------------------------------------------------------
__global__ __launch_bounds__(256) void softmax_rows(float* __restrict__ attn)
{
    float* row = attn + (size_t)blockIdx.x * NTOK;
    const int t = threadIdx.x;
    __shared__ float red[256];

    float4 x = ((const float4*)row)[t];
    float m = fmaxf(fmaxf(x.x, x.y), fmaxf(x.z, x.w));
    red[t] = m;
    __syncthreads();
    #pragma unroll
    for (int s = 128; s >= 1; s >>= 1) {
        if (t < s) red[t] = fmaxf(red[t], red[t + s]);
        __syncthreads();
    }
    m = red[0];
    __syncthreads();

    x.x = __expf(x.x - m);
    x.y = __expf(x.y - m);
    x.z = __expf(x.z - m);
    x.w = __expf(x.w - m);
    red[t] = x.x + x.y + x.z + x.w;
    __syncthreads();
    #pragma unroll
    for (int s = 128; s >= 1; s >>= 1) {
        if (t < s) red[t] += red[t + s];
        __syncthreads();
    }
    const float inv = 1.0f / red[0];
    x.x *= inv; x.y *= inv; x.z *= inv; x.w *= inv;
    ((float4*)row)[t] = x;
}

// ---------------------------------------------------------------------------
// Combined biases: b_qc = W_q b_cnn + b_q ; b_ke = W_k b_eff + b_k ;
//                  b_ve = W_v b_eff + b_v   (all K = 512)
// ---------------------------------------------------------------------------
__global__ void combine_bias(
    const float* __restrict__ Wq, const float* __restrict__ bcnn, const float* __restrict__ bq,
    const float* __restrict__ Wk, const float* __restrict__ bk,
    const float* __restrict__ Wv, const float* __restrict__ bv,
    const float* __restrict__ beff)
{
    const int o = threadIdx.x;
    if (blockIdx.x == 0) {
        float s = bq[o];
        for (int c = 0; c < HIDC; c++) s += Wq[o * HIDC + c] * bcnn[c];
        g_bqc[o] = s;
    } else if (blockIdx.x == 1) {
        float s = bk[o];
        for (int c = 0; c < HIDC; c++) s += Wk[o * HIDC + c] * beff[c];
        g_bke[o] = s;
    } else {
        float s = bv[o];
        for (int c = 0; c < HIDC; c++) s += Wv[o * HIDC + c] * beff[c];
        g_bve[o] = s;
    }
}

// ---------------------------------------------------------------------------
// Launch
// ---------------------------------------------------------------------------
extern "C" void kernel_launch(void* const* d_in, const int* in_sizes, int n_in,
                              void* d_out, int out_size)
{
    const float* xc = (const float*)d_in[0];   // cnn_features       [32,512,1024]
    const float* xe = (const float*)d_in[1];   // efficient_features [32,1280,1024]
    const float* Wc = (const float*)d_in[2];   // W_cnn [512,512]
    const float* bc = (const float*)d_in[3];
    const float* We = (const float*)d_in[4];   // W_eff [512,1280]
    const float* be = (const float*)d_in[5];
    const float* Wq = (const float*)d_in[6];
    const float* bq = (const float*)d_in[7];
    const float* Wk = (const float*)d_in[8];
    const float* bk = (const float*)d_in[9];
    const float* Wv = (const float*)d_in[10];
    const float* bv = (const float*)d_in[11];
    const float* gamma = (const float*)d_in[12];
    float* out = (float*)d_out;

    float *p_Wqc, *p_Wke, *p_Wve, *p_bqc, *p_bke, *p_bve, *p_q, *p_k, *p_v, *p_attn;
    cudaGetSymbolAddress((void**)&p_Wqc, g_Wqc);
    cudaGetSymbolAddress((void**)&p_Wke, g_Wke);
    cudaGetSymbolAddress((void**)&p_Wve, g_Wve);
    cudaGetSymbolAddress((void**)&p_bqc, g_bqc);
    cudaGetSymbolAddress((void**)&p_bke, g_bke);
    cudaGetSymbolAddress((void**)&p_bve, g_bve);
    cudaGetSymbolAddress((void**)&p_q, g_q);
    cudaGetSymbolAddress((void**)&p_k, g_k);
    cudaGetSymbolAddress((void**)&p_v, g_v);
    cudaGetSymbolAddress((void**)&p_attn, g_attn);

    const size_t sX  = (size_t)HIDC * NTOK;   // per-batch stride for [512,1024]
    const size_t sXe = (size_t)CEFF * NTOK;   // per-batch stride for [1280,1024]
    const size_t sAt = (size_t)NTOK * NTOK;

    // 1-3: fold weights: W_qc = W_q @ W_cnn, W_ke = W_k @ W_eff, W_ve = W_v @ W_eff
    sgemm_nn<<<dim3(4, 4, 1), 256>>>(Wq, HIDC, Wc, HIDC, 0, p_Wqc, HIDC, 0, nullptr, HIDC);
    sgemm_nn<<<dim3(10, 4, 1), 256>>>(Wk, HIDC, We, CEFF, 0, p_Wke, CEFF, 0, nullptr, HIDC);
    sgemm_nn<<<dim3(10, 4, 1), 256>>>(Wv, HIDC, We, CEFF, 0, p_Wve, CEFF, 0, nullptr, HIDC);

    // 4: combined biases
    combine_bias<<<3, HIDC>>>(Wq, bc, bq, Wk, bk, Wv, bv, be);

    // 5: cnn_proj -> staged directly in d_out (residual source)
    sgemm_nn<<<dim3(8, 4, BATCH), 256>>>(Wc, HIDC, xc, NTOK, sX, out, NTOK, sX, bc, HIDC);

    // 6: q = W_qc @ x_cnn + b_qc
    sgemm_nn<<<dim3(8, 4, BATCH), 256>>>(p_Wqc, HIDC, xc, NTOK, sX, p_q, NTOK, sX, p_bqc, HIDC);

    // 7-8: k, v directly from efficient_features (eff_proj eliminated)
    sgemm_nn<<<dim3(8, 4, BATCH), 256>>>(p_Wke, CEFF, xe, NTOK, sXe, p_k, NTOK, sX, p_bke, CEFF);
    sgemm_nn<<<dim3(8, 4, BATCH), 256>>>(p_Wve, CEFF, xe, NTOK, sXe, p_v, NTOK, sX, p_bve, CEFF);

    // 9: logits = q^T k
    sgemm_tn_logits<<<dim3(8, 8, BATCH), 256>>>(p_q, p_k, p_attn);

    // 10: row softmax
    softmax_rows<<<BATCH * NTOK, 256>>>(p_attn);

    // 11: out = gamma * (attn @ v^T) + cnn_proj
    sgemm_nt_out<<<dim3(8, 4, BATCH), 256>>>(p_v, p_attn, out, gamma);
}

// round 2
// speedup vs baseline: 1.0010x; 1.0010x over previous
#include <cuda_runtime.h>
#include <cstddef>

// Problem constants (fixed shapes)
#define HIDC   512
#define NTOK   1024
#define BATCH  32
#define CEFF   1280

// ---------------------------------------------------------------------------
// Scratch (no allocations allowed -> __device__ globals)
// ---------------------------------------------------------------------------
__device__ float g_Wqc[HIDC * HIDC];          // W_q @ W_cnn        [512,512]
__device__ float g_Wke[HIDC * CEFF];          // W_k @ W_eff        [512,1280]
__device__ float g_Wve[HIDC * CEFF];          // W_v @ W_eff        [512,1280]
__device__ float g_bqc[HIDC];
__device__ float g_bke[HIDC];
__device__ float g_bve[HIDC];
__device__ float g_q[(size_t)BATCH * HIDC * NTOK];     // [b][c][n]
__device__ float g_k[(size_t)BATCH * HIDC * NTOK];     // [b][c][n]
__device__ float g_v[(size_t)BATCH * HIDC * NTOK];     // [b][c][n]
__device__ float g_attn[(size_t)BATCH * NTOK * NTOK];  // [b][n][m]

// ---------------------------------------------------------------------------
// Generic NN SGEMM:  C[b][m][n] = sum_k A[m][k] * B[b][k][n] (+ bias[m])
// A row-major [M,K] (weights, unbatched), B row-major [K,N] batched.
// BM=BN=128, BK=8, 256 threads, 8x8 per-thread microtile.
// All dims assumed multiples of tile sizes (true for this problem).
// ---------------------------------------------------------------------------
__global__ __launch_bounds__(256) void sgemm_nn(
    const float* __restrict__ A, int lda,
    const float* __restrict__ B, int ldb, size_t sB,
    float* __restrict__ C, int ldc, size_t sC,
    const float* __restrict__ bias, int K)
{
    __shared__ float As[8][128];
    __shared__ float Bs[8][128];

    const int tid = threadIdx.x;
    const int bx = blockIdx.x, by = blockIdx.y, bz = blockIdx.z;

    const float* Ab = A + (size_t)by * 128 * lda;
    const float* Bb = B + (size_t)bz * sB + (size_t)bx * 128;
    float*       Cb = C + (size_t)bz * sC + (size_t)by * 128 * ldc + (size_t)bx * 128;

    // A tile load: 128 rows x 8 k, one float4 per thread, transpose into As
    const int a_r = tid >> 1;            // 0..127
    const int a_c = (tid & 1) * 4;       // 0 or 4
    // B tile load: 8 k rows x 128 n, one float4 per thread
    const int b_r = tid >> 5;            // 0..7
    const int b_c = (tid & 31) * 4;      // 0..124

    const int tx = tid & 15;             // n fragment
    const int ty = tid >> 4;             // m fragment

    float acc[8][8];
    #pragma unroll
    for (int i = 0; i < 8; i++)
        #pragma unroll
        for (int j = 0; j < 8; j++) acc[i][j] = 0.f;

    for (int k0 = 0; k0 < K; k0 += 8) {
        float4 av = *(const float4*)(Ab + (size_t)a_r * lda + k0 + a_c);
        As[a_c + 0][a_r] = av.x;
        As[a_c + 1][a_r] = av.y;
        As[a_c + 2][a_r] = av.z;
        As[a_c + 3][a_r] = av.w;
        *(float4*)(&Bs[b_r][b_c]) = *(const float4*)(Bb + (size_t)(k0 + b_r) * ldb + b_c);
        __syncthreads();

        #pragma unroll
        for (int k = 0; k < 8; k++) {
            float4 a0 = *(const float4*)(&As[k][ty * 8]);
            float4 a1 = *(const float4*)(&As[k][ty * 8 + 4]);
            float4 b0 = *(const float4*)(&Bs[k][tx * 8]);
            float4 b1 = *(const float4*)(&Bs[k][tx * 8 + 4]);
            float ra[8] = {a0.x, a0.y, a0.z, a0.w, a1.x, a1.y, a1.z, a1.w};
            float rb[8] = {b0.x, b0.y, b0.z, b0.w, b1.x, b1.y, b1.z, b1.w};
            #pragma unroll
            for (int i = 0; i < 8; i++)
                #pragma unroll
                for (int j = 0; j < 8; j++)
                    acc[i][j] += ra[i] * rb[j];
        }
        __syncthreads();
    }

    #pragma unroll
    for (int i = 0; i < 8; i++) {
        float bv = bias ? bias[by * 128 + ty * 8 + i] : 0.f;
        float* cr = Cb + (size_t)(ty * 8 + i) * ldc + tx * 8;
        float4 o0, o1;
        o0.x = acc[i][0] + bv; o0.y = acc[i][1] + bv;
        o0.z = acc[i][2] + bv; o0.w = acc[i][3] + bv;
        o1.x = acc[i][4] + bv; o1.y = acc[i][5] + bv;
        o1.z = acc[i][6] + bv; o1.w = acc[i][7] + bv;
        *(float4*)(cr)     = o0;
        *(float4*)(cr + 4) = o1;
    }
}

// ---------------------------------------------------------------------------
// TN SGEMM (attention logits): C[b][n][m] = sum_c Q[b][c][n] * Kt[b][c][m]
// Both operands K-major [C,N] with ld = 1024. Fixed sizes M=N=1024, K=512.
// ---------------------------------------------------------------------------
__global__ __launch_bounds__(256) void sgemm_tn_logits(
    const float* __restrict__ Q, const float* __restrict__ Kt,
    float* __restrict__ C)
{
    __shared__ float As[8][128];
    __shared__ float Bs[8][128];

    const int tid = threadIdx.x;
    const float* Ab = Q  + (size_t)blockIdx.z * (HIDC * NTOK) + (size_t)blockIdx.y * 128;
    const float* Bb = Kt + (size_t)blockIdx.z * (HIDC * NTOK) + (size_t)blockIdx.x * 128;
    float*       Cb = C  + (size_t)blockIdx.z * (NTOK * NTOK)
                         + (size_t)blockIdx.y * 128 * NTOK + (size_t)blockIdx.x * 128;

    const int l_r = tid >> 5;            // 0..7
    const int l_c = (tid & 31) * 4;      // 0..124
    const int tx = tid & 15;
    const int ty = tid >> 4;

    float acc[8][8];
    #pragma unroll
    for (int i = 0; i < 8; i++)
        #pragma unroll
        for (int j = 0; j < 8; j++) acc[i][j] = 0.f;

    for (int k0 = 0; k0 < HIDC; k0 += 8) {
        *(float4*)(&As[l_r][l_c]) = *(const float4*)(Ab + (size_t)(k0 + l_r) * NTOK + l_c);
        *(float4*)(&Bs[l_r][l_c]) = *(const float4*)(Bb + (size_t)(k0 + l_r) * NTOK + l_c);
        __syncthreads();

        #pragma unroll
        for (int k = 0; k < 8; k++) {
            float4 a0 = *(const float4*)(&As[k][ty * 8]);
            float4 a1 = *(const float4*)(&As[k][ty * 8 + 4]);
            float4 b0 = *(const float4*)(&Bs[k][tx * 8]);
            float4 b1 = *(const float4*)(&Bs[k][tx * 8 + 4]);
            float ra[8] = {a0.x, a0.y, a0.z, a0.w, a1.x, a1.y, a1.z, a1.w};
            float rb[8] = {b0.x, b0.y, b0.z, b0.w, b1.x, b1.y, b1.z, b1.w};
            #pragma unroll
            for (int i = 0; i < 8; i++)
                #pragma unroll
                for (int j = 0; j < 8; j++)
                    acc[i][j] += ra[i] * rb[j];
        }
        __syncthreads();
    }

    #pragma unroll
    for (int i = 0; i < 8; i++) {
        float* cr = Cb + (size_t)(ty * 8 + i) * NTOK + tx * 8;
        *(float4*)(cr)     = make_float4(acc[i][0], acc[i][1], acc[i][2], acc[i][3]);
        *(float4*)(cr + 4) = make_float4(acc[i][4], acc[i][5], acc[i][6], acc[i][7]);
    }
}

// ---------------------------------------------------------------------------
// NT SGEMM + epilogue: out[b][c][n] = gamma * sum_m V[b][c][m]*attn[b][n][m]
//                                     + out[b][c][n]   (cnn_proj residual)
// A = V [C=512, M=1024] m-contig; B = attn [N=1024, M=1024] m-contig.
// Fixed: Mdim(c)=512, Ndim(n)=1024, K(m)=1024.
// ---------------------------------------------------------------------------
__global__ __launch_bounds__(256) void sgemm_nt_out(
    const float* __restrict__ V, const float* __restrict__ Attn,
    float* __restrict__ Out, const float* __restrict__ gamma)
{
    __shared__ float As[8][128];
    __shared__ float Bs[8][128];

    const int tid = threadIdx.x;
    const float* Ab = V    + (size_t)blockIdx.z * (HIDC * NTOK) + (size_t)blockIdx.y * 128 * NTOK;
    const float* Bb = Attn + (size_t)blockIdx.z * (NTOK * NTOK) + (size_t)blockIdx.x * 128 * NTOK;
    float*       Cb = Out  + (size_t)blockIdx.z * (HIDC * NTOK)
                           + (size_t)blockIdx.y * 128 * NTOK + (size_t)blockIdx.x * 128;

    const int a_r = tid >> 1;           // 0..127 (row within tile)
    const int a_c = (tid & 1) * 4;      // 0 or 4 (k offset)
    const int tx = tid & 15;
    const int ty = tid >> 4;

    float acc[8][8];
    #pragma unroll
    for (int i = 0; i < 8; i++)
        #pragma unroll
        for (int j = 0; j < 8; j++) acc[i][j] = 0.f;

    for (int k0 = 0; k0 < NTOK; k0 += 8) {
        float4 av = *(const float4*)(Ab + (size_t)a_r * NTOK + k0 + a_c);
        As[a_c + 0][a_r] = av.x;
        As[a_c + 1][a_r] = av.y;
        As[a_c + 2][a_r] = av.z;
        As[a_c + 3][a_r] = av.w;
        float4 bv = *(const float4*)(Bb + (size_t)a_r * NTOK + k0 + a_c);
        Bs[a_c + 0][a_r] = bv.x;
        Bs[a_c + 1][a_r] = bv.y;
        Bs[a_c + 2][a_r] = bv.z;
        Bs[a_c + 3][a_r] = bv.w;
        __syncthreads();

        #pragma unroll
        for (int k = 0; k < 8; k++) {
            float4 a0 = *(const float4*)(&As[k][ty * 8]);
            float4 a1 = *(const float4*)(&As[k][ty * 8 + 4]);
            float4 b0 = *(const float4*)(&Bs[k][tx * 8]);
            float4 b1 = *(const float4*)(&Bs[k][tx * 8 + 4]);
            float ra[8] = {a0.x, a0.y, a0.z, a0.w, a1.x, a1.y, a1.z, a1.w};
            float rb[8] = {b0.x, b0.y, b0.z, b0.w, b1.x, b1.y, b1.z, b1.w};
            #pragma unroll
            for (int i = 0; i < 8; i++)
                #pragma unroll
                for (int j = 0; j < 8; j++)
                    acc[i][j] += ra[i] * rb[j];
        }
        __syncthreads();
    }

    const float g = gamma[0];
    #pragma unroll
    for (int i = 0; i < 8; i++) {
        float* cr = Cb + (size_t)(ty * 8 + i) * NTOK + tx * 8;
        float4 c0 = *(const float4*)(cr);
        float4 c1 = *(const float4*)(cr + 4);
        c0.x = g * acc[i][0] + c0.x; c0.y = g * acc[i][1] + c0.y;
        c0.z = g * acc[i][2] + c0.z; c0.w = g * acc[i][3] + c0.w;
        c1.x = g * acc[i][4] + c1.x; c1.y = g * acc[i][5] + c1.y;
        c1.z = g * acc[i][6] + c1.z; c1.w = g * acc[i][7] + c1.w;
        *(float4*)(cr)     = c0;
        *(float4*)(cr + 4) = c1;
    }
}

// ---------------------------------------------------------------------------
// Row softmax over attn [B*N rows, N cols]. One block of 256 threads per row.
// ---------------------------------------------------------------------------
__global__ __launch_bounds__(256) void softmax_rows(float* __restrict__ attn)
{
    float* row = attn + (size_t)blockIdx.x * NTOK;
    const int t = threadIdx.x;
    __shared__ float red[256];

    float4 x = ((const float4*)row)[t];
    float m = fmaxf(fmaxf(x.x, x.y), fmaxf(x.z, x.w));
    red[t] = m;
    __syncthreads();
    #pragma unroll
    for (int s = 128; s >= 1; s >>= 1) {
        if (t < s) red[t] = fmaxf(red[t], red[t + s]);
        __syncthreads();
    }
    m = red[0];
    __syncthreads();

    x.x = __expf(x.x - m);
    x.y = __expf(x.y - m);
    x.z = __expf(x.z - m);
    x.w = __expf(x.w - m);
    red[t] = x.x + x.y + x.z + x.w;
    __syncthreads();
    #pragma unroll
    for (int s = 128; s >= 1; s >>= 1) {
        if (t < s) red[t] += red[t + s];
        __syncthreads();
    }
    const float inv = 1.0f / red[0];
    x.x *= inv; x.y *= inv; x.z *= inv; x.w *= inv;
    ((float4*)row)[t] = x;
}

// ---------------------------------------------------------------------------
// Combined biases: b_qc = W_q b_cnn + b_q ; b_ke = W_k b_eff + b_k ;
//                  b_ve = W_v b_eff + b_v   (all K = 512)
// ---------------------------------------------------------------------------
__global__ void combine_bias(
    const float* __restrict__ Wq, const float* __restrict__ bcnn, const float* __restrict__ bq,
    const float* __restrict__ Wk, const float* __restrict__ bk,
    const float* __restrict__ Wv, const float* __restrict__ bv,
    const float* __restrict__ beff)
{
    const int o = threadIdx.x;
    if (blockIdx.x == 0) {
        float s = bq[o];
        for (int c = 0; c < HIDC; c++) s += Wq[o * HIDC + c] * bcnn[c];
        g_bqc[o] = s;
    } else if (blockIdx.x == 1) {
        float s = bk[o];
        for (int c = 0; c < HIDC; c++) s += Wk[o * HIDC + c] * beff[c];
        g_bke[o] = s;
    } else {
        float s = bv[o];
        for (int c = 0; c < HIDC; c++) s += Wv[o * HIDC + c] * beff[c];
        g_bve[o] = s;
    }
}

// ---------------------------------------------------------------------------
// Launch
// ---------------------------------------------------------------------------
extern "C" void kernel_launch(void* const* d_in, const int* in_sizes, int n_in,
                              void* d_out, int out_size)
{
    const float* xc = (const float*)d_in[0];   // cnn_features       [32,512,1024]
    const float* xe = (const float*)d_in[1];   // efficient_features [32,1280,1024]
    const float* Wc = (const float*)d_in[2];   // W_cnn [512,512]
    const float* bc = (const float*)d_in[3];
    const float* We = (const float*)d_in[4];   // W_eff [512,1280]
    const float* be = (const float*)d_in[5];
    const float* Wq = (const float*)d_in[6];
    const float* bq = (const float*)d_in[7];
    const float* Wk = (const float*)d_in[8];
    const float* bk = (const float*)d_in[9];
    const float* Wv = (const float*)d_in[10];
    const float* bv = (const float*)d_in[11];
    const float* gamma = (const float*)d_in[12];
    float* out = (float*)d_out;

    float *p_Wqc, *p_Wke, *p_Wve, *p_bqc, *p_bke, *p_bve, *p_q, *p_k, *p_v, *p_attn;
    cudaGetSymbolAddress((void**)&p_Wqc, g_Wqc);
    cudaGetSymbolAddress((void**)&p_Wke, g_Wke);
    cudaGetSymbolAddress((void**)&p_Wve, g_Wve);
    cudaGetSymbolAddress((void**)&p_bqc, g_bqc);
    cudaGetSymbolAddress((void**)&p_bke, g_bke);
    cudaGetSymbolAddress((void**)&p_bve, g_bve);
    cudaGetSymbolAddress((void**)&p_q, g_q);
    cudaGetSymbolAddress((void**)&p_k, g_k);
    cudaGetSymbolAddress((void**)&p_v, g_v);
    cudaGetSymbolAddress((void**)&p_attn, g_attn);

    const size_t sX  = (size_t)HIDC * NTOK;   // per-batch stride for [512,1024]
    const size_t sXe = (size_t)CEFF * NTOK;   // per-batch stride for [1280,1024]
    const size_t sAt = (size_t)NTOK * NTOK;

    // 1-3: fold weights: W_qc = W_q @ W_cnn, W_ke = W_k @ W_eff, W_ve = W_v @ W_eff
    sgemm_nn<<<dim3(4, 4, 1), 256>>>(Wq, HIDC, Wc, HIDC, 0, p_Wqc, HIDC, 0, nullptr, HIDC);
    sgemm_nn<<<dim3(10, 4, 1), 256>>>(Wk, HIDC, We, CEFF, 0, p_Wke, CEFF, 0, nullptr, HIDC);
    sgemm_nn<<<dim3(10, 4, 1), 256>>>(Wv, HIDC, We, CEFF, 0, p_Wve, CEFF, 0, nullptr, HIDC);

    // 4: combined biases
    combine_bias<<<3, HIDC>>>(Wq, bc, bq, Wk, bk, Wv, bv, be);

    // 5: cnn_proj -> staged directly in d_out (residual source)
    sgemm_nn<<<dim3(8, 4, BATCH), 256>>>(Wc, HIDC, xc, NTOK, sX, out, NTOK, sX, bc, HIDC);

    // 6: q = W_qc @ x_cnn + b_qc
    sgemm_nn<<<dim3(8, 4, BATCH), 256>>>(p_Wqc, HIDC, xc, NTOK, sX, p_q, NTOK, sX, p_bqc, HIDC);

    // 7-8: k, v directly from efficient_features (eff_proj eliminated)
    sgemm_nn<<<dim3(8, 4, BATCH), 256>>>(p_Wke, CEFF, xe, NTOK, sXe, p_k, NTOK, sX, p_bke, CEFF);
    sgemm_nn<<<dim3(8, 4, BATCH), 256>>>(p_Wve, CEFF, xe, NTOK, sXe, p_v, NTOK, sX, p_bve, CEFF);

    // 9: logits = q^T k
    sgemm_tn_logits<<<dim3(8, 8, BATCH), 256>>>(p_q, p_k, p_attn);

    // 10: row softmax
    softmax_rows<<<BATCH * NTOK, 256>>>(p_attn);

    // 11: out = gamma * (attn @ v^T) + cnn_proj
    sgemm_nt_out<<<dim3(8, 4, BATCH), 256>>>(p_v, p_attn, out, gamma);
}

// round 4
// speedup vs baseline: 3.7770x; 3.7732x over previous
#include <cuda_runtime.h>
#include <cuda_bf16.h>
#include <cstdint>
#include <cstddef>

#define HIDC 512
#define NTOK 1024
#define BATCH 32
#define CEFF 1280

typedef __nv_bfloat16 bf16;

// ------------------------- scratch ---------------------------------------
__device__ float g_Wqc[HIDC * HIDC];
__device__ float g_Wke[HIDC * CEFF];
__device__ float g_Wve[HIDC * CEFF];
__device__ float g_bqc[HIDC], g_bke[HIDC], g_bve[HIDC];

__device__ bf16 g_Wc_h[HIDC * HIDC], g_Wc_l[HIDC * HIDC];
__device__ bf16 g_Wqc_h[HIDC * HIDC];
__device__ bf16 g_Wke_h[HIDC * CEFF], g_Wve_h[HIDC * CEFF];

__device__ bf16 g_XcT_h[(size_t)BATCH * NTOK * HIDC];
__device__ bf16 g_XcT_l[(size_t)BATCH * NTOK * HIDC];
__device__ bf16 g_XeT_h[(size_t)BATCH * NTOK * CEFF];

__device__ bf16  g_qb[(size_t)BATCH * NTOK * HIDC];   // [b][n][c]
__device__ bf16  g_kb[(size_t)BATCH * NTOK * HIDC];   // [b][m][c]
__device__ bf16  g_vb[(size_t)BATCH * HIDC * NTOK];   // [b][c][m]
__device__ float g_attn[(size_t)BATCH * NTOK * NTOK]; // [b][n][m]
__device__ bf16  g_P[(size_t)BATCH * NTOK * NTOK];    // [b][n][m]

#define MMA_B16(D, A_, B_) \
    asm volatile("mma.sync.aligned.m16n8k16.row.col.f32.bf16.bf16.f32 " \
        "{%0,%1,%2,%3}, {%4,%5,%6,%7}, {%8,%9}, {%0,%1,%2,%3};" \
        : "+f"((D)[0]), "+f"((D)[1]), "+f"((D)[2]), "+f"((D)[3]) \
        : "r"((A_)[0]), "r"((A_)[1]), "r"((A_)[2]), "r"((A_)[3]), \
          "r"((B_)[0]), "r"((B_)[1]))

// ---------------------------------------------------------------------------
// bf16 HMMA GEMM: C[M0+128, N0+128] = sum_K A[m,k] * B[n,k]  (both K-major)
// SPLIT adds Ah*Bl + Al*Bh (split-bf16 fp32 emulation).
// BIASM: 0 none, 1 bias[M-row], 2 bias[N-col]
// OUTM:  0 fp32 row-major; 1 bf16 row-major; 2 fp32 transposed RMW (g*D + C)
// Tiles: BM=BN=128, BK=32. 256 threads, 8 warps (2m x 4n), warp tile 64x32.
// smem padded to 40 elems/row -> conflict-free 32-bit fragment loads.
// ---------------------------------------------------------------------------
template<bool SPLIT, int BIASM, int OUTM>
__global__ __launch_bounds__(256) void mma_gemm(
    const bf16* __restrict__ Ah, const bf16* __restrict__ Al,
    const bf16* __restrict__ Bh, const bf16* __restrict__ Bl,
    int lda, int ldb, size_t sA, size_t sB,
    void* __restrict__ Cout, int ldc, size_t sC,
    const float* __restrict__ bias, const float* __restrict__ gamma, int K)
{
    __shared__ bf16 sAh[128 * 40];
    __shared__ bf16 sBh[128 * 40];
    __shared__ bf16 sAl[SPLIT ? 128 * 40 : 8];
    __shared__ bf16 sBl[SPLIT ? 128 * 40 : 8];

    const int tid = threadIdx.x;
    const int wid = tid >> 5;
    const int lid = tid & 31;
    const int wm = wid & 1;          // 0..1 (64-row half)
    const int wn = wid >> 1;         // 0..3 (32-col quarter)
    const int g  = lid >> 2;         // 0..7
    const int tc = (lid & 3) * 2;    // 0,2,4,6

    const int M0 = blockIdx.y * 128;
    const int N0 = blockIdx.x * 128;
    const int b  = blockIdx.z;

    const bf16* pA = Ah + (size_t)b * sA + (size_t)M0 * lda;
    const bf16* pB = Bh + (size_t)b * sB + (size_t)N0 * ldb;
    const bf16* pAl = SPLIT ? (Al + (size_t)b * sA + (size_t)M0 * lda) : nullptr;
    const bf16* pBl = SPLIT ? (Bl + (size_t)b * sB + (size_t)N0 * ldb) : nullptr;

    float acc[4][4][4];
    #pragma unroll
    for (int i = 0; i < 4; i++)
        #pragma unroll
        for (int j = 0; j < 4; j++)
            #pragma unroll
            for (int r = 0; r < 4; r++) acc[i][j][r] = 0.f;

    const int lr = tid >> 2;          // 0..63 base row for loads
    const int lc = (tid & 3) * 8;     // 0,8,16,24 (element offset)

    for (int k0 = 0; k0 < K; k0 += 32) {
        // load 128x32 tiles (each thread: 2 rows x 8 elems per tile)
        #pragma unroll
        for (int h = 0; h < 2; h++) {
            int r = lr + h * 64;
            *(uint4*)&sAh[r * 40 + lc] = *(const uint4*)(pA + (size_t)r * lda + k0 + lc);
            *(uint4*)&sBh[r * 40 + lc] = *(const uint4*)(pB + (size_t)r * ldb + k0 + lc);
            if (SPLIT) {
                *(uint4*)&sAl[r * 40 + lc] = *(const uint4*)(pAl + (size_t)r * lda + k0 + lc);
                *(uint4*)&sBl[r * 40 + lc] = *(const uint4*)(pBl + (size_t)r * ldb + k0 + lc);
            }
        }
        __syncthreads();

        #pragma unroll
        for (int ks = 0; ks < 32; ks += 16) {
            uint32_t a[4][4], bb[4][2];
            #pragma unroll
            for (int mt = 0; mt < 4; mt++) {
                int m = wm * 64 + mt * 16;
                a[mt][0] = *(const uint32_t*)&sAh[(m + g) * 40 + ks + tc];
                a[mt][1] = *(const uint32_t*)&sAh[(m + 8 + g) * 40 + ks + tc];
                a[mt][2] = *(const uint32_t*)&sAh[(m + g) * 40 + ks + 8 + tc];
                a[mt][3] = *(const uint32_t*)&sAh[(m + 8 + g) * 40 + ks + 8 + tc];
            }
            #pragma unroll
            for (int nt = 0; nt < 4; nt++) {
                int n = wn * 32 + nt * 8;
                bb[nt][0] = *(const uint32_t*)&sBh[(n + g) * 40 + ks + tc];
                bb[nt][1] = *(const uint32_t*)&sBh[(n + g) * 40 + ks + 8 + tc];
            }
            #pragma unroll
            for (int mt = 0; mt < 4; mt++)
                #pragma unroll
                for (int nt = 0; nt < 4; nt++)
                    MMA_B16(acc[mt][nt], a[mt], bb[nt]);

            if (SPLIT) {
                uint32_t al[4][4], bl[4][2];
                #pragma unroll
                for (int mt = 0; mt < 4; mt++) {
                    int m = wm * 64 + mt * 16;
                    al[mt][0] = *(const uint32_t*)&sAl[(m + g) * 40 + ks + tc];
                    al[mt][1] = *(const uint32_t*)&sAl[(m + 8 + g) * 40 + ks + tc];
                    al[mt][2] = *(const uint32_t*)&sAl[(m + g) * 40 + ks + 8 + tc];
                    al[mt][3] = *(const uint32_t*)&sAl[(m + 8 + g) * 40 + ks + 8 + tc];
                }
                #pragma unroll
                for (int nt = 0; nt < 4; nt++) {
                    int n = wn * 32 + nt * 8;
                    bl[nt][0] = *(const uint32_t*)&sBl[(n + g) * 40 + ks + tc];
                    bl[nt][1] = *(const uint32_t*)&sBl[(n + g) * 40 + ks + 8 + tc];
                }
                #pragma unroll
                for (int mt = 0; mt < 4; mt++)
                    #pragma unroll
                    for (int nt = 0; nt < 4; nt++) {
                        MMA_B16(acc[mt][nt], a[mt], bl[nt]);
                        MMA_B16(acc[mt][nt], al[mt], bb[nt]);
                    }
            }
        }
        __syncthreads();
    }

    // ---------------- epilogue ----------------
    const float gm = (OUTM == 2) ? gamma[0] : 0.f;
    #pragma unroll
    for (int mt = 0; mt < 4; mt++) {
        #pragma unroll
        for (int nt = 0; nt < 4; nt++) {
            const int grow = M0 + wm * 64 + mt * 16 + g;
            const int gcol = N0 + wn * 32 + nt * 8 + tc;
            float d0 = acc[mt][nt][0], d1 = acc[mt][nt][1];
            float d2 = acc[mt][nt][2], d3 = acc[mt][nt][3];

            if (OUTM == 0) {
                float* C = (float*)Cout + (size_t)b * sC;
                if (BIASM == 1) {
                    float br0 = __ldg(bias + grow), br1 = __ldg(bias + grow + 8);
                    d0 += br0; d1 += br0; d2 += br1; d3 += br1;
                } else if (BIASM == 2) {
                    float bc0 = __ldg(bias + gcol), bc1 = __ldg(bias + gcol + 1);
                    d0 += bc0; d1 += bc1; d2 += bc0; d3 += bc1;
                }
                *(float2*)(C + (size_t)grow * ldc + gcol) = make_float2(d0, d1);
                *(float2*)(C + (size_t)(grow + 8) * ldc + gcol) = make_float2(d2, d3);
            } else if (OUTM == 1) {
                bf16* C = (bf16*)Cout + (size_t)b * sC;
                if (BIASM == 1) {
                    float br0 = __ldg(bias + grow), br1 = __ldg(bias + grow + 8);
                    d0 += br0; d1 += br0; d2 += br1; d3 += br1;
                } else if (BIASM == 2) {
                    float bc0 = __ldg(bias + gcol), bc1 = __ldg(bias + gcol + 1);
                    d0 += bc0; d1 += bc1; d2 += bc0; d3 += bc1;
                }
                __nv_bfloat162 h0 = __floats2bfloat162_rn(d0, d1);
                __nv_bfloat162 h1 = __floats2bfloat162_rn(d2, d3);
                *(__nv_bfloat162*)(C + (size_t)grow * ldc + gcol) = h0;
                *(__nv_bfloat162*)(C + (size_t)(grow + 8) * ldc + gcol) = h1;
            } else {
                float* C = (float*)Cout + (size_t)b * sC;
                float* p00 = C + (size_t)gcol * ldc + grow;
                float* p01 = C + (size_t)(gcol + 1) * ldc + grow;
                p00[0] = gm * d0 + p00[0];
                p01[0] = gm * d1 + p01[0];
                p00[8] = gm * d2 + p00[8];
                p01[8] = gm * d3 + p01[8];
            }
        }
    }
}

// transpose fp32 [b][C][1024] -> bf16 hi(/lo) [b][1024][C]
__global__ __launch_bounds__(256) void transpose_split(
    const float* __restrict__ in, bf16* __restrict__ hi, bf16* __restrict__ lo, int C)
{
    __shared__ float t[32][33];
    const int c0 = blockIdx.x * 32, n0 = blockIdx.y * 32, b = blockIdx.z;
    const float* pin = in + (size_t)b * C * NTOK;
    const int tx = threadIdx.x & 31, ty = threadIdx.x >> 5;
    #pragma unroll
    for (int i = 0; i < 4; i++)
        t[ty + i * 8][tx] = pin[(size_t)(c0 + ty + i * 8) * NTOK + n0 + tx];
    __syncthreads();
    #pragma unroll
    for (int i = 0; i < 4; i++) {
        float x = t[tx][ty + i * 8];
        bf16 h = __float2bfloat16(x);
        size_t o = (size_t)b * NTOK * C + (size_t)(n0 + ty + i * 8) * C + c0 + tx;
        hi[o] = h;
        if (lo) lo[o] = __float2bfloat16(x - __bfloat162float(h));
    }
}

__global__ void split_bf16(const float* __restrict__ in, bf16* __restrict__ hi,
                           bf16* __restrict__ lo, int n)
{
    int i = blockIdx.x * 256 + threadIdx.x;
    if (i < n) {
        float x = in[i];
        bf16 h = __float2bfloat16(x);
        hi[i] = h;
        if (lo) lo[i] = __float2bfloat16(x - __bfloat162float(h));
    }
}

// fp32 fold GEMM: C[M,N] = A[M,K] @ B[K,N] (64x64 tiles)
__global__ __launch_bounds__(256) void sgemm64(
    const float* __restrict__ A, int lda, const float* __restrict__ B, int ldb,
    float* __restrict__ C, int ldc, int K)
{
    __shared__ float As[16][64];
    __shared__ float Bs[16][64];
    const int tid = threadIdx.x;
    const float* Ab = A + (size_t)blockIdx.y * 64 * lda;
    const float* Bb = B + blockIdx.x * 64;
    float* Cb = C + (size_t)blockIdx.y * 64 * ldc + blockIdx.x * 64;
    const int ar = tid >> 2, ac = (tid & 3) * 4;
    const int br = tid >> 4, bc = (tid & 15) * 4;
    const int tx = tid & 15, ty = tid >> 4;

    float acc[4][4];
    #pragma unroll
    for (int i = 0; i < 4; i++)
        #pragma unroll
        for (int j = 0; j < 4; j++) acc[i][j] = 0.f;

    for (int k0 = 0; k0 < K; k0 += 16) {
        float4 av = *(const float4*)(Ab + (size_t)ar * lda + k0 + ac);
        As[ac + 0][ar] = av.x; As[ac + 1][ar] = av.y;
        As[ac + 2][ar] = av.z; As[ac + 3][ar] = av.w;
        *(float4*)(&Bs[br][bc]) = *(const float4*)(Bb + (size_t)(k0 + br) * ldb + bc);
        __syncthreads();
        #pragma unroll
        for (int k = 0; k < 16; k++) {
            float4 a = *(const float4*)(&As[k][ty * 4]);
            float4 bv = *(const float4*)(&Bs[k][tx * 4]);
            float ra[4] = {a.x, a.y, a.z, a.w};
            float rb[4] = {bv.x, bv.y, bv.z, bv.w};
            #pragma unroll
            for (int i = 0; i < 4; i++)
                #pragma unroll
                for (int j = 0; j < 4; j++) acc[i][j] += ra[i] * rb[j];
        }
        __syncthreads();
    }
    #pragma unroll
    for (int i = 0; i < 4; i++)
        *(float4*)(Cb + (size_t)(ty * 4 + i) * ldc + tx * 4) =
            make_float4(acc[i][0], acc[i][1], acc[i][2], acc[i][3]);
}

__global__ void combine_bias2(
    const float* __restrict__ Wq, const float* __restrict__ bcnn, const float* __restrict__ bq,
    const float* __restrict__ Wk, const float* __restrict__ bk,
    const float* __restrict__ Wv, const float* __restrict__ bv,
    const float* __restrict__ beff,
    float* __restrict__ bqc, float* __restrict__ bke, float* __restrict__ bve)
{
    const int which = blockIdx.y;
    const int o = blockIdx.x * 8 + (threadIdx.x >> 5);
    const int l = threadIdx.x & 31;
    const float* W   = (which == 0) ? Wq : (which == 1) ? Wk : Wv;
    const float* vin = (which == 0) ? bcnn : beff;
    const float* add = (which == 0) ? bq : (which == 1) ? bk : bv;
    float s = 0.f;
    for (int c = l; c < HIDC; c += 32) s += W[(size_t)o * HIDC + c] * vin[c];
    #pragma unroll
    for (int d = 16; d; d >>= 1) s += __shfl_xor_sync(0xFFFFFFFFu, s, d);
    if (l == 0) {
        float* dst = (which == 0) ? bqc : (which == 1) ? bke : bve;
        dst[o] = s + add[o];
    }
}

// row softmax: fp32 logits -> bf16 probs
__global__ __launch_bounds__(256) void softmax_rows(
    const float* __restrict__ attn, bf16* __restrict__ P)
{
    const float* row = attn + (size_t)blockIdx.x * NTOK;
    const int t = threadIdx.x;
    __shared__ float red[8];

    float4 x = ((const float4*)row)[t];
    float m = fmaxf(fmaxf(x.x, x.y), fmaxf(x.z, x.w));
    #pragma unroll
    for (int d = 16; d; d >>= 1) m = fmaxf(m, __shfl_xor_sync(0xFFFFFFFFu, m, d));
    if ((t & 31) == 0) red[t >> 5] = m;
    __syncthreads();
    m = red[0];
    #pragma unroll
    for (int i = 1; i < 8; i++) m = fmaxf(m, red[i]);

    x.x = __expf(x.x - m); x.y = __expf(x.y - m);
    x.z = __expf(x.z - m); x.w = __expf(x.w - m);
    float s = x.x + x.y + x.z + x.w;
    #pragma unroll
    for (int d = 16; d; d >>= 1) s += __shfl_xor_sync(0xFFFFFFFFu, s, d);
    __syncthreads();
    if ((t & 31) == 0) red[t >> 5] = s;
    __syncthreads();
    s = 0.f;
    #pragma unroll
    for (int i = 0; i < 8; i++) s += red[i];
    const float inv = 1.0f / s;

    __nv_bfloat162* pr = (__nv_bfloat162*)(P + (size_t)blockIdx.x * NTOK);
    pr[t * 2 + 0] = __floats2bfloat162_rn(x.x * inv, x.y * inv);
    pr[t * 2 + 1] = __floats2bfloat162_rn(x.z * inv, x.w * inv);
}

// ------------------------------ launch ------------------------------------
extern "C" void kernel_launch(void* const* d_in, const int* in_sizes, int n_in,
                              void* d_out, int out_size)
{
    const float* xc = (const float*)d_in[0];
    const float* xe = (const float*)d_in[1];
    const float* Wc = (const float*)d_in[2];
    const float* bc = (const float*)d_in[3];
    const float* We = (const float*)d_in[4];
    const float* be = (const float*)d_in[5];
    const float* Wq = (const float*)d_in[6];
    const float* bq = (const float*)d_in[7];
    const float* Wk = (const float*)d_in[8];
    const float* bk = (const float*)d_in[9];
    const float* Wv = (const float*)d_in[10];
    const float* bv = (const float*)d_in[11];
    const float* gamma = (const float*)d_in[12];
    float* out = (float*)d_out;

    float *p_Wqc, *p_Wke, *p_Wve, *p_bqc, *p_bke, *p_bve, *p_attn;
    bf16 *p_Wc_h, *p_Wc_l, *p_Wqc_h, *p_Wke_h, *p_Wve_h;
    bf16 *p_XcT_h, *p_XcT_l, *p_XeT_h, *p_qb, *p_kb, *p_vb, *p_P;
    cudaGetSymbolAddress((void**)&p_Wqc, g_Wqc);
    cudaGetSymbolAddress((void**)&p_Wke, g_Wke);
    cudaGetSymbolAddress((void**)&p_Wve, g_Wve);
    cudaGetSymbolAddress((void**)&p_bqc, g_bqc);
    cudaGetSymbolAddress((void**)&p_bke, g_bke);
    cudaGetSymbolAddress((void**)&p_bve, g_bve);
    cudaGetSymbolAddress((void**)&p_attn, g_attn);
    cudaGetSymbolAddress((void**)&p_Wc_h, g_Wc_h);
    cudaGetSymbolAddress((void**)&p_Wc_l, g_Wc_l);
    cudaGetSymbolAddress((void**)&p_Wqc_h, g_Wqc_h);
    cudaGetSymbolAddress((void**)&p_Wke_h, g_Wke_h);
    cudaGetSymbolAddress((void**)&p_Wve_h, g_Wve_h);
    cudaGetSymbolAddress((void**)&p_XcT_h, g_XcT_h);
    cudaGetSymbolAddress((void**)&p_XcT_l, g_XcT_l);
    cudaGetSymbolAddress((void**)&p_XeT_h, g_XeT_h);
    cudaGetSymbolAddress((void**)&p_qb, g_qb);
    cudaGetSymbolAddress((void**)&p_kb, g_kb);
    cudaGetSymbolAddress((void**)&p_vb, g_vb);
    cudaGetSymbolAddress((void**)&p_P, g_P);

    const size_t sXc = (size_t)NTOK * HIDC;
    const size_t sXe = (size_t)NTOK * CEFF;
    const size_t sO  = (size_t)HIDC * NTOK;
    const size_t sAt = (size_t)NTOK * NTOK;

    // weight folds (fp32)
    sgemm64<<<dim3(8, 8), 256>>>(Wq, HIDC, Wc, HIDC, p_Wqc, HIDC, HIDC);
    sgemm64<<<dim3(20, 8), 256>>>(Wk, HIDC, We, CEFF, p_Wke, CEFF, HIDC);
    sgemm64<<<dim3(20, 8), 256>>>(Wv, HIDC, We, CEFF, p_Wve, CEFF, HIDC);
    combine_bias2<<<dim3(64, 3), 256>>>(Wq, bc, bq, Wk, bk, Wv, bv, be, p_bqc, p_bke, p_bve);

    // conversions
    split_bf16<<<1024, 256>>>(Wc, p_Wc_h, p_Wc_l, HIDC * HIDC);
    split_bf16<<<1024, 256>>>(p_Wqc, p_Wqc_h, nullptr, HIDC * HIDC);
    split_bf16<<<2560, 256>>>(p_Wke, p_Wke_h, nullptr, HIDC * CEFF);
    split_bf16<<<2560, 256>>>(p_Wve, p_Wve_h, nullptr, HIDC * CEFF);

    // transposes
    transpose_split<<<dim3(16, 32, BATCH), 256>>>(xc, p_XcT_h, p_XcT_l, HIDC);
    transpose_split<<<dim3(40, 32, BATCH), 256>>>(xe, p_XeT_h, nullptr, CEFF);

    // cnn_proj (split bf16) -> d_out fp32 [b][c][n]
    mma_gemm<true, 1, 0><<<dim3(8, 4, BATCH), 256>>>(
        p_Wc_h, p_Wc_l, p_XcT_h, p_XcT_l, HIDC, HIDC, 0, sXc,
        out, NTOK, sO, bc, nullptr, HIDC);

    // q[b][n][c] bf16
    mma_gemm<false, 2, 1><<<dim3(4, 8, BATCH), 256>>>(
        p_XcT_h, nullptr, p_Wqc_h, nullptr, HIDC, HIDC, sXc, 0,
        p_qb, HIDC, sXc, p_bqc, nullptr, HIDC);

    // k[b][m][c] bf16
    mma_gemm<false, 2, 1><<<dim3(4, 8, BATCH), 256>>>(
        p_XeT_h, nullptr, p_Wke_h, nullptr, CEFF, CEFF, sXe, 0,
        p_kb, HIDC, sXc, p_bke, nullptr, CEFF);

    // v[b][c][m] bf16
    mma_gemm<false, 1, 1><<<dim3(8, 4, BATCH), 256>>>(
        p_Wve_h, nullptr, p_XeT_h, nullptr, CEFF, CEFF, 0, sXe,
        p_vb, NTOK, sO, p_bve, nullptr, CEFF);

    // logits[b][n][m] fp32
    mma_gemm<false, 0, 0><<<dim3(8, 8, BATCH), 256>>>(
        p_qb, nullptr, p_kb, nullptr, HIDC, HIDC, sXc, sXc,
        p_attn, NTOK, sAt, nullptr, nullptr, HIDC);

    // softmax -> P bf16
    softmax_rows<<<BATCH * NTOK, 256>>>(p_attn, p_P);

    // out[b][c][n] += gamma * (P @ v^T)   (transposed RMW)
    mma_gemm<false, 0, 2><<<dim3(4, 8, BATCH), 256>>>(
        p_P, nullptr, p_vb, nullptr, NTOK, NTOK, sAt, sO,
        out, NTOK, sO, nullptr, gamma, NTOK);
}

// round 5
// speedup vs baseline: 4.4504x; 1.1783x over previous
#include <cuda_runtime.h>
#include <cuda_bf16.h>
#include <cstdint>
#include <cstddef>

#define HIDC 512
#define NTOK 1024
#define BATCH 32
#define CEFF 1280

typedef __nv_bfloat16 bf16;

// ------------------------- scratch ---------------------------------------
__device__ float g_Wqc[HIDC * HIDC];
__device__ float g_Wke[HIDC * CEFF];
__device__ float g_Wve[HIDC * CEFF];
__device__ float g_bqc[HIDC], g_bke[HIDC], g_bve[HIDC];

__device__ bf16 g_Wc_h[HIDC * HIDC], g_Wc_l[HIDC * HIDC];
__device__ bf16 g_Wqc_h[HIDC * HIDC];
__device__ bf16 g_Wke_h[HIDC * CEFF], g_Wve_h[HIDC * CEFF];

__device__ bf16 g_XcT_h[(size_t)BATCH * NTOK * HIDC];
__device__ bf16 g_XcT_l[(size_t)BATCH * NTOK * HIDC];
__device__ bf16 g_XeT_h[(size_t)BATCH * NTOK * CEFF];

__device__ bf16  g_qb[(size_t)BATCH * NTOK * HIDC];   // [b][n][c]
__device__ bf16  g_kb[(size_t)BATCH * NTOK * HIDC];   // [b][m][c]
__device__ bf16  g_vb[(size_t)BATCH * HIDC * NTOK];   // [b][c][m]
__device__ float g_attn[(size_t)BATCH * NTOK * NTOK]; // [b][n][m]
__device__ bf16  g_P[(size_t)BATCH * NTOK * NTOK];    // [b][n][m]

#define MMA_B16(D, A_, B_) \
    asm volatile("mma.sync.aligned.m16n8k16.row.col.f32.bf16.bf16.f32 " \
        "{%0,%1,%2,%3}, {%4,%5,%6,%7}, {%8,%9}, {%0,%1,%2,%3};" \
        : "+f"((D)[0]), "+f"((D)[1]), "+f"((D)[2]), "+f"((D)[3]) \
        : "r"((A_)[0]), "r"((A_)[1]), "r"((A_)[2]), "r"((A_)[3]), \
          "r"((B_)[0]), "r"((B_)[1]))

#define LDSM4(R0, R1, R2, R3, ADDR) \
    asm volatile("ldmatrix.sync.aligned.m8n8.x4.shared.b16 {%0,%1,%2,%3}, [%4];" \
        : "=r"(R0), "=r"(R1), "=r"(R2), "=r"(R3) : "r"(ADDR))

__device__ __forceinline__ uint32_t smem_u32(const void* p) {
    uint32_t a;
    asm("{ .reg .u64 t; cvta.to.shared.u64 t, %1; cvt.u32.u64 %0, t; }" : "=r"(a) : "l"(p));
    return a;
}
__device__ __forceinline__ void cp16(uint32_t dst, const void* src) {
    asm volatile("cp.async.cg.shared.global [%0], [%1], 16;" :: "r"(dst), "l"(src));
}
__device__ __forceinline__ void cp_commit() {
    asm volatile("cp.async.commit_group;" ::: "memory");
}
template<int N> __device__ __forceinline__ void cp_wait() {
    asm volatile("cp.async.wait_group %0;" :: "n"(N) : "memory");
}

// ---------------------------------------------------------------------------
// bf16 HMMA GEMM, 2-stage cp.async pipeline + ldmatrix fragment loads.
// C[M0+128, N0+128] = sum_K A[m,k] * B[n,k]  (both K-major)
// SPLIT adds Ah*Bl + Al*Bh.  BIASM: 0 none, 1 bias[row], 2 bias[col]
// OUTM: 0 fp32 row-major; 1 bf16 row-major; 2 fp32 transposed RMW (g*D+C)
// BM=BN=128, BK=32, 256 thr, 8 warps (2m x 4n), warp tile 64x32.
// smem row stride 40 elems (80B) -> conflict-free ldmatrix.
// Stage layout (bytes): A@0 (10240), B@10240; SPLIT: Al@20480, Bl@30720.
// ---------------------------------------------------------------------------
template<bool SPLIT, int BIASM, int OUTM>
__global__ __launch_bounds__(256) void mma_gemm(
    const bf16* __restrict__ Ah, const bf16* __restrict__ Al,
    const bf16* __restrict__ Bh, const bf16* __restrict__ Bl,
    int lda, int ldb, size_t sA, size_t sB,
    void* __restrict__ Cout, int ldc, size_t sC,
    const float* __restrict__ bias, const float* __restrict__ gamma, int K)
{
    extern __shared__ char dynsm[];
    constexpr int STAGE = SPLIT ? 40960 : 20480;
    const uint32_t sm0 = smem_u32(dynsm);

    const int tid = threadIdx.x;
    const int wid = tid >> 5;
    const int lid = tid & 31;
    const int wm = wid & 1;
    const int wn = wid >> 1;
    const int g  = lid >> 2;
    const int tc = (lid & 3) * 2;

    const int M0 = blockIdx.y * 128;
    const int N0 = blockIdx.x * 128;
    const int b  = blockIdx.z;

    const bf16* pA = Ah + (size_t)b * sA + (size_t)M0 * lda;
    const bf16* pB = Bh + (size_t)b * sB + (size_t)N0 * ldb;
    const bf16* pAl = SPLIT ? (Al + (size_t)b * sA + (size_t)M0 * lda) : nullptr;
    const bf16* pBl = SPLIT ? (Bl + (size_t)b * sB + (size_t)N0 * ldb) : nullptr;

    // copy indices: each thread 2 rows x 8 elems per tile
    const int lr = tid >> 2;
    const int lc = (tid & 3) * 8;

    // ldmatrix per-thread offsets (bytes, relative to tile base)
    const int l8  = lid & 7;
    const int mi1 = (lid >> 3) & 1;
    const int mi2 = (lid >> 4) & 1;
    const uint32_t offA = (uint32_t)(((wm * 64 + mi1 * 8 + l8) * 40 + mi2 * 8) * 2);
    const uint32_t offB = (uint32_t)(((wn * 32 + mi2 * 8 + l8) * 40 + mi1 * 8) * 2);

    float acc[4][4][4];
    #pragma unroll
    for (int i = 0; i < 4; i++)
        #pragma unroll
        for (int j = 0; j < 4; j++)
            #pragma unroll
            for (int r = 0; r < 4; r++) acc[i][j][r] = 0.f;

    const int nk = K >> 5;

    auto copy_stage = [&](int buf, int kt) {
        const int k0 = kt << 5;
        const uint32_t sb = sm0 + buf * STAGE;
        #pragma unroll
        for (int h = 0; h < 2; h++) {
            const int r = lr + h * 64;
            const uint32_t so = (uint32_t)((r * 40 + lc) * 2);
            cp16(sb + so,         pA + (size_t)r * lda + k0 + lc);
            cp16(sb + 10240 + so, pB + (size_t)r * ldb + k0 + lc);
            if (SPLIT) {
                cp16(sb + 20480 + so, pAl + (size_t)r * lda + k0 + lc);
                cp16(sb + 30720 + so, pBl + (size_t)r * ldb + k0 + lc);
            }
        }
        cp_commit();
    };

    copy_stage(0, 0);

    for (int kt = 0; kt < nk; kt++) {
        if (kt + 1 < nk) {
            copy_stage((kt + 1) & 1, kt + 1);
            cp_wait<1>();
        } else {
            cp_wait<0>();
        }
        __syncthreads();

        const uint32_t sb = sm0 + (kt & 1) * STAGE;
        #pragma unroll
        for (int ks = 0; ks < 32; ks += 16) {
            uint32_t a[4][4], bb[4][2];
            #pragma unroll
            for (int mt = 0; mt < 4; mt++)
                LDSM4(a[mt][0], a[mt][1], a[mt][2], a[mt][3],
                      sb + offA + mt * 1280 + ks * 2);
            #pragma unroll
            for (int p = 0; p < 2; p++)
                LDSM4(bb[2 * p][0], bb[2 * p][1], bb[2 * p + 1][0], bb[2 * p + 1][1],
                      sb + 10240 + offB + p * 1280 + ks * 2);
            #pragma unroll
            for (int mt = 0; mt < 4; mt++)
                #pragma unroll
                for (int nt = 0; nt < 4; nt++)
                    MMA_B16(acc[mt][nt], a[mt], bb[nt]);

            if (SPLIT) {
                uint32_t al[4][4], bl[4][2];
                #pragma unroll
                for (int mt = 0; mt < 4; mt++)
                    LDSM4(al[mt][0], al[mt][1], al[mt][2], al[mt][3],
                          sb + 20480 + offA + mt * 1280 + ks * 2);
                #pragma unroll
                for (int p = 0; p < 2; p++)
                    LDSM4(bl[2 * p][0], bl[2 * p][1], bl[2 * p + 1][0], bl[2 * p + 1][1],
                          sb + 30720 + offB + p * 1280 + ks * 2);
                #pragma unroll
                for (int mt = 0; mt < 4; mt++)
                    #pragma unroll
                    for (int nt = 0; nt < 4; nt++) {
                        MMA_B16(acc[mt][nt], a[mt], bl[nt]);
                        MMA_B16(acc[mt][nt], al[mt], bb[nt]);
                    }
            }
        }
        __syncthreads();
    }

    // ---------------- epilogue ----------------
    const float gm = (OUTM == 2) ? gamma[0] : 0.f;
    #pragma unroll
    for (int mt = 0; mt < 4; mt++) {
        #pragma unroll
        for (int nt = 0; nt < 4; nt++) {
            const int grow = M0 + wm * 64 + mt * 16 + g;
            const int gcol = N0 + wn * 32 + nt * 8 + tc;
            float d0 = acc[mt][nt][0], d1 = acc[mt][nt][1];
            float d2 = acc[mt][nt][2], d3 = acc[mt][nt][3];

            if (OUTM == 0) {
                float* C = (float*)Cout + (size_t)b * sC;
                if (BIASM == 1) {
                    float br0 = __ldg(bias + grow), br1 = __ldg(bias + grow + 8);
                    d0 += br0; d1 += br0; d2 += br1; d3 += br1;
                } else if (BIASM == 2) {
                    float bc0 = __ldg(bias + gcol), bc1 = __ldg(bias + gcol + 1);
                    d0 += bc0; d1 += bc1; d2 += bc0; d3 += bc1;
                }
                *(float2*)(C + (size_t)grow * ldc + gcol) = make_float2(d0, d1);
                *(float2*)(C + (size_t)(grow + 8) * ldc + gcol) = make_float2(d2, d3);
            } else if (OUTM == 1) {
                bf16* C = (bf16*)Cout + (size_t)b * sC;
                if (BIASM == 1) {
                    float br0 = __ldg(bias + grow), br1 = __ldg(bias + grow + 8);
                    d0 += br0; d1 += br0; d2 += br1; d3 += br1;
                } else if (BIASM == 2) {
                    float bc0 = __ldg(bias + gcol), bc1 = __ldg(bias + gcol + 1);
                    d0 += bc0; d1 += bc1; d2 += bc0; d3 += bc1;
                }
                *(__nv_bfloat162*)(C + (size_t)grow * ldc + gcol) = __floats2bfloat162_rn(d0, d1);
                *(__nv_bfloat162*)(C + (size_t)(grow + 8) * ldc + gcol) = __floats2bfloat162_rn(d2, d3);
            } else {
                float* C = (float*)Cout + (size_t)b * sC;
                float* p00 = C + (size_t)gcol * ldc + grow;
                float* p01 = C + (size_t)(gcol + 1) * ldc + grow;
                p00[0] = gm * d0 + p00[0];
                p01[0] = gm * d1 + p01[0];
                p00[8] = gm * d2 + p00[8];
                p01[8] = gm * d3 + p01[8];
            }
        }
    }
}

// transpose fp32 [b][C][1024] -> bf16 hi(/lo) [b][1024][C]
__global__ __launch_bounds__(256) void transpose_split(
    const float* __restrict__ in, bf16* __restrict__ hi, bf16* __restrict__ lo, int C)
{
    __shared__ float t[32][33];
    const int c0 = blockIdx.x * 32, n0 = blockIdx.y * 32, b = blockIdx.z;
    const float* pin = in + (size_t)b * C * NTOK;
    const int tx = threadIdx.x & 31, ty = threadIdx.x >> 5;
    #pragma unroll
    for (int i = 0; i < 4; i++)
        t[ty + i * 8][tx] = pin[(size_t)(c0 + ty + i * 8) * NTOK + n0 + tx];
    __syncthreads();
    #pragma unroll
    for (int i = 0; i < 4; i++) {
        float x = t[tx][ty + i * 8];
        bf16 h = __float2bfloat16(x);
        size_t o = (size_t)b * NTOK * C + (size_t)(n0 + ty + i * 8) * C + c0 + tx;
        hi[o] = h;
        if (lo) lo[o] = __float2bfloat16(x - __bfloat162float(h));
    }
}

__global__ void split_bf16(const float* __restrict__ in, bf16* __restrict__ hi,
                           bf16* __restrict__ lo, int n)
{
    int i = blockIdx.x * 256 + threadIdx.x;
    if (i < n) {
        float x = in[i];
        bf16 h = __float2bfloat16(x);
        hi[i] = h;
        if (lo) lo[i] = __float2bfloat16(x - __bfloat162float(h));
    }
}

// fp32 fold GEMM: C[M,N] = A[M,K] @ B[K,N] (64x64 tiles)
__global__ __launch_bounds__(256) void sgemm64(
    const float* __restrict__ A, int lda, const float* __restrict__ B, int ldb,
    float* __restrict__ C, int ldc, int K)
{
    __shared__ float As[16][64];
    __shared__ float Bs[16][64];
    const int tid = threadIdx.x;
    const float* Ab = A + (size_t)blockIdx.y * 64 * lda;
    const float* Bb = B + blockIdx.x * 64;
    float* Cb = C + (size_t)blockIdx.y * 64 * ldc + blockIdx.x * 64;
    const int ar = tid >> 2, ac = (tid & 3) * 4;
    const int br = tid >> 4, bc = (tid & 15) * 4;
    const int tx = tid & 15, ty = tid >> 4;

    float acc[4][4];
    #pragma unroll
    for (int i = 0; i < 4; i++)
        #pragma unroll
        for (int j = 0; j < 4; j++) acc[i][j] = 0.f;

    for (int k0 = 0; k0 < K; k0 += 16) {
        float4 av = *(const float4*)(Ab + (size_t)ar * lda + k0 + ac);
        As[ac + 0][ar] = av.x; As[ac + 1][ar] = av.y;
        As[ac + 2][ar] = av.z; As[ac + 3][ar] = av.w;
        *(float4*)(&Bs[br][bc]) = *(const float4*)(Bb + (size_t)(k0 + br) * ldb + bc);
        __syncthreads();
        #pragma unroll
        for (int k = 0; k < 16; k++) {
            float4 a = *(const float4*)(&As[k][ty * 4]);
            float4 bv = *(const float4*)(&Bs[k][tx * 4]);
            float ra[4] = {a.x, a.y, a.z, a.w};
            float rb[4] = {bv.x, bv.y, bv.z, bv.w};
            #pragma unroll
            for (int i = 0; i < 4; i++)
                #pragma unroll
                for (int j = 0; j < 4; j++) acc[i][j] += ra[i] * rb[j];
        }
        __syncthreads();
    }
    #pragma unroll
    for (int i = 0; i < 4; i++)
        *(float4*)(Cb + (size_t)(ty * 4 + i) * ldc + tx * 4) =
            make_float4(acc[i][0], acc[i][1], acc[i][2], acc[i][3]);
}

__global__ void combine_bias2(
    const float* __restrict__ Wq, const float* __restrict__ bcnn, const float* __restrict__ bq,
    const float* __restrict__ Wk, const float* __restrict__ bk,
    const float* __restrict__ Wv, const float* __restrict__ bv,
    const float* __restrict__ beff,
    float* __restrict__ bqc, float* __restrict__ bke, float* __restrict__ bve)
{
    const int which = blockIdx.y;
    const int o = blockIdx.x * 8 + (threadIdx.x >> 5);
    const int l = threadIdx.x & 31;
    const float* W   = (which == 0) ? Wq : (which == 1) ? Wk : Wv;
    const float* vin = (which == 0) ? bcnn : beff;
    const float* add = (which == 0) ? bq : (which == 1) ? bk : bv;
    float s = 0.f;
    for (int c = l; c < HIDC; c += 32) s += W[(size_t)o * HIDC + c] * vin[c];
    #pragma unroll
    for (int d = 16; d; d >>= 1) s += __shfl_xor_sync(0xFFFFFFFFu, s, d);
    if (l == 0) {
        float* dst = (which == 0) ? bqc : (which == 1) ? bke : bve;
        dst[o] = s + add[o];
    }
}

// row softmax: fp32 logits -> bf16 probs
__global__ __launch_bounds__(256) void softmax_rows(
    const float* __restrict__ attn, bf16* __restrict__ P)
{
    const float* row = attn + (size_t)blockIdx.x * NTOK;
    const int t = threadIdx.x;
    __shared__ float red[8];

    float4 x = ((const float4*)row)[t];
    float m = fmaxf(fmaxf(x.x, x.y), fmaxf(x.z, x.w));
    #pragma unroll
    for (int d = 16; d; d >>= 1) m = fmaxf(m, __shfl_xor_sync(0xFFFFFFFFu, m, d));
    if ((t & 31) == 0) red[t >> 5] = m;
    __syncthreads();
    m = red[0];
    #pragma unroll
    for (int i = 1; i < 8; i++) m = fmaxf(m, red[i]);

    x.x = __expf(x.x - m); x.y = __expf(x.y - m);
    x.z = __expf(x.z - m); x.w = __expf(x.w - m);
    float s = x.x + x.y + x.z + x.w;
    #pragma unroll
    for (int d = 16; d; d >>= 1) s += __shfl_xor_sync(0xFFFFFFFFu, s, d);
    __syncthreads();
    if ((t & 31) == 0) red[t >> 5] = s;
    __syncthreads();
    s = 0.f;
    #pragma unroll
    for (int i = 0; i < 8; i++) s += red[i];
    const float inv = 1.0f / s;

    __nv_bfloat162* pr = (__nv_bfloat162*)(P + (size_t)blockIdx.x * NTOK);
    pr[t * 2 + 0] = __floats2bfloat162_rn(x.x * inv, x.y * inv);
    pr[t * 2 + 1] = __floats2bfloat162_rn(x.z * inv, x.w * inv);
}

// ------------------------------ launch ------------------------------------
extern "C" void kernel_launch(void* const* d_in, const int* in_sizes, int n_in,
                              void* d_out, int out_size)
{
    const float* xc = (const float*)d_in[0];
    const float* xe = (const float*)d_in[1];
    const float* Wc = (const float*)d_in[2];
    const float* bc = (const float*)d_in[3];
    const float* We = (const float*)d_in[4];
    const float* be = (const float*)d_in[5];
    const float* Wq = (const float*)d_in[6];
    const float* bq = (const float*)d_in[7];
    const float* Wk = (const float*)d_in[8];
    const float* bk = (const float*)d_in[9];
    const float* Wv = (const float*)d_in[10];
    const float* bv = (const float*)d_in[11];
    const float* gamma = (const float*)d_in[12];
    float* out = (float*)d_out;

    float *p_Wqc, *p_Wke, *p_Wve, *p_bqc, *p_bke, *p_bve, *p_attn;
    bf16 *p_Wc_h, *p_Wc_l, *p_Wqc_h, *p_Wke_h, *p_Wve_h;
    bf16 *p_XcT_h, *p_XcT_l, *p_XeT_h, *p_qb, *p_kb, *p_vb, *p_P;
    cudaGetSymbolAddress((void**)&p_Wqc, g_Wqc);
    cudaGetSymbolAddress((void**)&p_Wke, g_Wke);
    cudaGetSymbolAddress((void**)&p_Wve, g_Wve);
    cudaGetSymbolAddress((void**)&p_bqc, g_bqc);
    cudaGetSymbolAddress((void**)&p_bke, g_bke);
    cudaGetSymbolAddress((void**)&p_bve, g_bve);
    cudaGetSymbolAddress((void**)&p_attn, g_attn);
    cudaGetSymbolAddress((void**)&p_Wc_h, g_Wc_h);
    cudaGetSymbolAddress((void**)&p_Wc_l, g_Wc_l);
    cudaGetSymbolAddress((void**)&p_Wqc_h, g_Wqc_h);
    cudaGetSymbolAddress((void**)&p_Wke_h, g_Wke_h);
    cudaGetSymbolAddress((void**)&p_Wve_h, g_Wve_h);
    cudaGetSymbolAddress((void**)&p_XcT_h, g_XcT_h);
    cudaGetSymbolAddress((void**)&p_XcT_l, g_XcT_l);
    cudaGetSymbolAddress((void**)&p_XeT_h, g_XeT_h);
    cudaGetSymbolAddress((void**)&p_qb, g_qb);
    cudaGetSymbolAddress((void**)&p_kb, g_kb);
    cudaGetSymbolAddress((void**)&p_vb, g_vb);
    cudaGetSymbolAddress((void**)&p_P, g_P);

    const int SM_PLAIN = 40960;
    const int SM_SPLIT = 81920;
    static bool attrs_set = false;
    cudaFuncSetAttribute(mma_gemm<true, 1, 0>, cudaFuncAttributeMaxDynamicSharedMemorySize, SM_SPLIT);
    cudaFuncSetAttribute(mma_gemm<false, 2, 1>, cudaFuncAttributeMaxDynamicSharedMemorySize, SM_PLAIN);
    cudaFuncSetAttribute(mma_gemm<false, 1, 1>, cudaFuncAttributeMaxDynamicSharedMemorySize, SM_PLAIN);
    cudaFuncSetAttribute(mma_gemm<false, 0, 0>, cudaFuncAttributeMaxDynamicSharedMemorySize, SM_PLAIN);
    cudaFuncSetAttribute(mma_gemm<false, 0, 2>, cudaFuncAttributeMaxDynamicSharedMemorySize, SM_PLAIN);
    (void)attrs_set;

    const size_t sXc = (size_t)NTOK * HIDC;
    const size_t sXe = (size_t)NTOK * CEFF;
    const size_t sO  = (size_t)HIDC * NTOK;
    const size_t sAt = (size_t)NTOK * NTOK;

    // weight folds (fp32)
    sgemm64<<<dim3(8, 8), 256>>>(Wq, HIDC, Wc, HIDC, p_Wqc, HIDC, HIDC);
    sgemm64<<<dim3(20, 8), 256>>>(Wk, HIDC, We, CEFF, p_Wke, CEFF, HIDC);
    sgemm64<<<dim3(20, 8), 256>>>(Wv, HIDC, We, CEFF, p_Wve, CEFF, HIDC);
    combine_bias2<<<dim3(64, 3), 256>>>(Wq, bc, bq, Wk, bk, Wv, bv, be, p_bqc, p_bke, p_bve);

    // conversions
    split_bf16<<<1024, 256>>>(Wc, p_Wc_h, p_Wc_l, HIDC * HIDC);
    split_bf16<<<1024, 256>>>(p_Wqc, p_Wqc_h, nullptr, HIDC * HIDC);
    split_bf16<<<2560, 256>>>(p_Wke, p_Wke_h, nullptr, HIDC * CEFF);
    split_bf16<<<2560, 256>>>(p_Wve, p_Wve_h, nullptr, HIDC * CEFF);

    // transposes
    transpose_split<<<dim3(16, 32, BATCH), 256>>>(xc, p_XcT_h, p_XcT_l, HIDC);
    transpose_split<<<dim3(40, 32, BATCH), 256>>>(xe, p_XeT_h, nullptr, CEFF);

    // cnn_proj (split bf16) -> d_out fp32 [b][c][n]
    mma_gemm<true, 1, 0><<<dim3(8, 4, BATCH), 256, SM_SPLIT>>>(
        p_Wc_h, p_Wc_l, p_XcT_h, p_XcT_l, HIDC, HIDC, 0, sXc,
        out, NTOK, sO, bc, nullptr, HIDC);

    // q[b][n][c] bf16
    mma_gemm<false, 2, 1><<<dim3(4, 8, BATCH), 256, SM_PLAIN>>>(
        p_XcT_h, nullptr, p_Wqc_h, nullptr, HIDC, HIDC, sXc, 0,
        p_qb, HIDC, sXc, p_bqc, nullptr, HIDC);

    // k[b][m][c] bf16
    mma_gemm<false, 2, 1><<<dim3(4, 8, BATCH), 256, SM_PLAIN>>>(
        p_XeT_h, nullptr, p_Wke_h, nullptr, CEFF, CEFF, sXe, 0,
        p_kb, HIDC, sXc, p_bke, nullptr, CEFF);

    // v[b][c][m] bf16
    mma_gemm<false, 1, 1><<<dim3(8, 4, BATCH), 256, SM_PLAIN>>>(
        p_Wve_h, nullptr, p_XeT_h, nullptr, CEFF, CEFF, 0, sXe,
        p_vb, NTOK, sO, p_bve, nullptr, CEFF);

    // logits[b][n][m] fp32
    mma_gemm<false, 0, 0><<<dim3(8, 8, BATCH), 256, SM_PLAIN>>>(
        p_qb, nullptr, p_kb, nullptr, HIDC, HIDC, sXc, sXc,
        p_attn, NTOK, sAt, nullptr, nullptr, HIDC);

    // softmax -> P bf16
    softmax_rows<<<BATCH * NTOK, 256>>>(p_attn, p_P);

    // out[b][c][n] += gamma * (P @ v^T)   (transposed RMW)
    mma_gemm<false, 0, 2><<<dim3(4, 8, BATCH), 256, SM_PLAIN>>>(
        p_P, nullptr, p_vb, nullptr, NTOK, NTOK, sAt, sO,
        out, NTOK, sO, nullptr, gamma, NTOK);
}

// round 6
// speedup vs baseline: 4.9071x; 1.1026x over previous
#include <cuda_runtime.h>
#include <cuda_bf16.h>
#include <cstdint>
#include <cstddef>

#define HIDC 512
#define NTOK 1024
#define BATCH 32
#define CEFF 1280

typedef __nv_bfloat16 bf16;

// ------------------------- scratch ---------------------------------------
__device__ float g_bqc[HIDC], g_bke[HIDC], g_bve[HIDC];
__device__ float g_rsum[(size_t)BATCH * NTOK];         // softmax row sums

__device__ bf16 g_Wq_h[HIDC * HIDC], g_Wk_h[HIDC * HIDC], g_Wv_h[HIDC * HIDC];
__device__ bf16 g_WcT[HIDC * HIDC];                    // Wc^T bf16
__device__ bf16 g_WeT[CEFF * HIDC];                    // We^T bf16
__device__ bf16 g_Wc_h[HIDC * HIDC], g_Wc_l[HIDC * HIDC];
__device__ bf16 g_Wqc_h[HIDC * HIDC];
__device__ bf16 g_Wke_h[HIDC * CEFF], g_Wve_h[HIDC * CEFF];

__device__ bf16 g_XcT_h[(size_t)BATCH * NTOK * HIDC];
__device__ bf16 g_XcT_l[(size_t)BATCH * NTOK * HIDC];
__device__ bf16 g_XeT_h[(size_t)BATCH * NTOK * CEFF];

__device__ bf16 g_qb[(size_t)BATCH * NTOK * HIDC];     // [b][n][c]
__device__ bf16 g_kb[(size_t)BATCH * NTOK * HIDC];     // [b][m][c]
__device__ bf16 g_vb[(size_t)BATCH * HIDC * NTOK];     // [b][c][m]
__device__ bf16 g_P[(size_t)BATCH * NTOK * NTOK];      // [b][n][m] unnormalized exp

#define MMA_B16(D, A_, B_) \
    asm volatile("mma.sync.aligned.m16n8k16.row.col.f32.bf16.bf16.f32 " \
        "{%0,%1,%2,%3}, {%4,%5,%6,%7}, {%8,%9}, {%0,%1,%2,%3};" \
        : "+f"((D)[0]), "+f"((D)[1]), "+f"((D)[2]), "+f"((D)[3]) \
        : "r"((A_)[0]), "r"((A_)[1]), "r"((A_)[2]), "r"((A_)[3]), \
          "r"((B_)[0]), "r"((B_)[1]))

#define LDSM4(R0, R1, R2, R3, ADDR) \
    asm volatile("ldmatrix.sync.aligned.m8n8.x4.shared.b16 {%0,%1,%2,%3}, [%4];" \
        : "=r"(R0), "=r"(R1), "=r"(R2), "=r"(R3) : "r"(ADDR))

__device__ __forceinline__ uint32_t smem_u32(const void* p) {
    uint32_t a;
    asm("{ .reg .u64 t; cvta.to.shared.u64 t, %1; cvt.u32.u64 %0, t; }" : "=r"(a) : "l"(p));
    return a;
}
__device__ __forceinline__ void cp16(uint32_t dst, const void* src) {
    asm volatile("cp.async.cg.shared.global [%0], [%1], 16;" :: "r"(dst), "l"(src));
}
__device__ __forceinline__ void cp_commit() {
    asm volatile("cp.async.commit_group;" ::: "memory");
}
template<int N> __device__ __forceinline__ void cp_wait() {
    asm volatile("cp.async.wait_group %0;" :: "n"(N) : "memory");
}

// ---------------------------------------------------------------------------
// bf16 HMMA GEMM, 2-stage cp.async pipeline + ldmatrix.
// C[M0+128, N0+128] = sum_K A[m,k] * B[n,k]  (both K-major)
// SPLIT adds Ah*Bl + Al*Bh.  BIASM: 0 none, 1 bias[row], 2 bias[col]
// OUTM: 0 fp32 row-major (+bias)
//       1 bf16 row-major (+bias)
//       3 bf16 row-major exp(D) + rowsum atomicAdd into bias (softmax pass 1)
//       4 fp32 transposed RMW: out[col][row] += gamma/rowsum[row] * D
// ---------------------------------------------------------------------------
template<bool SPLIT, int BIASM, int OUTM>
__global__ __launch_bounds__(256) void mma_gemm(
    const bf16* __restrict__ Ah, const bf16* __restrict__ Al,
    const bf16* __restrict__ Bh, const bf16* __restrict__ Bl,
    int lda, int ldb, size_t sA, size_t sB,
    void* __restrict__ Cout, int ldc, size_t sC,
    const float* __restrict__ bias, const float* __restrict__ gamma, int K)
{
    extern __shared__ char dynsm[];
    constexpr int STAGE = SPLIT ? 40960 : 20480;
    const uint32_t sm0 = smem_u32(dynsm);

    const int tid = threadIdx.x;
    const int wid = tid >> 5;
    const int lid = tid & 31;
    const int wm = wid & 1;
    const int wn = wid >> 1;
    const int g  = lid >> 2;
    const int tc = (lid & 3) * 2;

    const int M0 = blockIdx.y * 128;
    const int N0 = blockIdx.x * 128;
    const int b  = blockIdx.z;

    const bf16* pA = Ah + (size_t)b * sA + (size_t)M0 * lda;
    const bf16* pB = Bh + (size_t)b * sB + (size_t)N0 * ldb;
    const bf16* pAl = SPLIT ? (Al + (size_t)b * sA + (size_t)M0 * lda) : nullptr;
    const bf16* pBl = SPLIT ? (Bl + (size_t)b * sB + (size_t)N0 * ldb) : nullptr;

    const int lr = tid >> 2;
    const int lc = (tid & 3) * 8;

    const int l8  = lid & 7;
    const int mi1 = (lid >> 3) & 1;
    const int mi2 = (lid >> 4) & 1;
    const uint32_t offA = (uint32_t)(((wm * 64 + mi1 * 8 + l8) * 40 + mi2 * 8) * 2);
    const uint32_t offB = (uint32_t)(((wn * 32 + mi2 * 8 + l8) * 40 + mi1 * 8) * 2);

    float acc[4][4][4];
    #pragma unroll
    for (int i = 0; i < 4; i++)
        #pragma unroll
        for (int j = 0; j < 4; j++)
            #pragma unroll
            for (int r = 0; r < 4; r++) acc[i][j][r] = 0.f;

    const int nk = K >> 5;

    auto copy_stage = [&](int buf, int kt) {
        const int k0 = kt << 5;
        const uint32_t sb = sm0 + buf * STAGE;
        #pragma unroll
        for (int h = 0; h < 2; h++) {
            const int r = lr + h * 64;
            const uint32_t so = (uint32_t)((r * 40 + lc) * 2);
            cp16(sb + so,         pA + (size_t)r * lda + k0 + lc);
            cp16(sb + 10240 + so, pB + (size_t)r * ldb + k0 + lc);
            if (SPLIT) {
                cp16(sb + 20480 + so, pAl + (size_t)r * lda + k0 + lc);
                cp16(sb + 30720 + so, pBl + (size_t)r * ldb + k0 + lc);
            }
        }
        cp_commit();
    };

    copy_stage(0, 0);

    for (int kt = 0; kt < nk; kt++) {
        if (kt + 1 < nk) {
            copy_stage((kt + 1) & 1, kt + 1);
            cp_wait<1>();
        } else {
            cp_wait<0>();
        }
        __syncthreads();

        const uint32_t sb = sm0 + (kt & 1) * STAGE;
        #pragma unroll
        for (int ks = 0; ks < 32; ks += 16) {
            uint32_t a[4][4], bb[4][2];
            #pragma unroll
            for (int mt = 0; mt < 4; mt++)
                LDSM4(a[mt][0], a[mt][1], a[mt][2], a[mt][3],
                      sb + offA + mt * 1280 + ks * 2);
            #pragma unroll
            for (int p = 0; p < 2; p++)
                LDSM4(bb[2 * p][0], bb[2 * p][1], bb[2 * p + 1][0], bb[2 * p + 1][1],
                      sb + 10240 + offB + p * 1280 + ks * 2);
            #pragma unroll
            for (int mt = 0; mt < 4; mt++)
                #pragma unroll
                for (int nt = 0; nt < 4; nt++)
                    MMA_B16(acc[mt][nt], a[mt], bb[nt]);

            if (SPLIT) {
                uint32_t al[4][4], bl[4][2];
                #pragma unroll
                for (int mt = 0; mt < 4; mt++)
                    LDSM4(al[mt][0], al[mt][1], al[mt][2], al[mt][3],
                          sb + 20480 + offA + mt * 1280 + ks * 2);
                #pragma unroll
                for (int p = 0; p < 2; p++)
                    LDSM4(bl[2 * p][0], bl[2 * p][1], bl[2 * p + 1][0], bl[2 * p + 1][1],
                          sb + 30720 + offB + p * 1280 + ks * 2);
                #pragma unroll
                for (int mt = 0; mt < 4; mt++)
                    #pragma unroll
                    for (int nt = 0; nt < 4; nt++) {
                        MMA_B16(acc[mt][nt], a[mt], bl[nt]);
                        MMA_B16(acc[mt][nt], al[mt], bb[nt]);
                    }
            }
        }
        __syncthreads();
    }

    // ---------------- epilogue ----------------
    if (OUTM == 3) {
        // exp + P write + rowsum accumulation
        __shared__ float srow[128];
        float* rs = const_cast<float*>(bias) + (size_t)b * NTOK;
        if (tid < 128) srow[tid] = 0.f;
        __syncthreads();
        bf16* C = (bf16*)Cout + (size_t)b * sC;
        #pragma unroll
        for (int mt = 0; mt < 4; mt++) {
            const int grow = M0 + wm * 64 + mt * 16 + g;
            float rp0 = 0.f, rp1 = 0.f;
            #pragma unroll
            for (int nt = 0; nt < 4; nt++) {
                const int gcol = N0 + wn * 32 + nt * 8 + tc;
                float e0 = __expf(acc[mt][nt][0]);
                float e1 = __expf(acc[mt][nt][1]);
                float e2 = __expf(acc[mt][nt][2]);
                float e3 = __expf(acc[mt][nt][3]);
                *(__nv_bfloat162*)(C + (size_t)grow * ldc + gcol) = __floats2bfloat162_rn(e0, e1);
                *(__nv_bfloat162*)(C + (size_t)(grow + 8) * ldc + gcol) = __floats2bfloat162_rn(e2, e3);
                rp0 += e0 + e1;
                rp1 += e2 + e3;
            }
            rp0 += __shfl_xor_sync(0xFFFFFFFFu, rp0, 1);
            rp0 += __shfl_xor_sync(0xFFFFFFFFu, rp0, 2);
            rp1 += __shfl_xor_sync(0xFFFFFFFFu, rp1, 1);
            rp1 += __shfl_xor_sync(0xFFFFFFFFu, rp1, 2);
            if ((lid & 3) == 0) {
                atomicAdd(&srow[wm * 64 + mt * 16 + g], rp0);
                atomicAdd(&srow[wm * 64 + mt * 16 + 8 + g], rp1);
            }
        }
        __syncthreads();
        if (tid < 128) atomicAdd(rs + M0 + tid, srow[tid]);
        return;
    }

    const float gm = (OUTM == 4) ? gamma[0] : 0.f;
    #pragma unroll
    for (int mt = 0; mt < 4; mt++) {
        #pragma unroll
        for (int nt = 0; nt < 4; nt++) {
            const int grow = M0 + wm * 64 + mt * 16 + g;
            const int gcol = N0 + wn * 32 + nt * 8 + tc;
            float d0 = acc[mt][nt][0], d1 = acc[mt][nt][1];
            float d2 = acc[mt][nt][2], d3 = acc[mt][nt][3];

            if (OUTM == 0) {
                float* C = (float*)Cout + (size_t)b * sC;
                if (BIASM == 1) {
                    float br0 = __ldg(bias + grow), br1 = __ldg(bias + grow + 8);
                    d0 += br0; d1 += br0; d2 += br1; d3 += br1;
                } else if (BIASM == 2) {
                    float bc0 = __ldg(bias + gcol), bc1 = __ldg(bias + gcol + 1);
                    d0 += bc0; d1 += bc1; d2 += bc0; d3 += bc1;
                }
                *(float2*)(C + (size_t)grow * ldc + gcol) = make_float2(d0, d1);
                *(float2*)(C + (size_t)(grow + 8) * ldc + gcol) = make_float2(d2, d3);
            } else if (OUTM == 1) {
                bf16* C = (bf16*)Cout + (size_t)b * sC;
                if (BIASM == 1) {
                    float br0 = __ldg(bias + grow), br1 = __ldg(bias + grow + 8);
                    d0 += br0; d1 += br0; d2 += br1; d3 += br1;
                } else if (BIASM == 2) {
                    float bc0 = __ldg(bias + gcol), bc1 = __ldg(bias + gcol + 1);
                    d0 += bc0; d1 += bc1; d2 += bc0; d3 += bc1;
                }
                *(__nv_bfloat162*)(C + (size_t)grow * ldc + gcol) = __floats2bfloat162_rn(d0, d1);
                *(__nv_bfloat162*)(C + (size_t)(grow + 8) * ldc + gcol) = __floats2bfloat162_rn(d2, d3);
            } else { // OUTM == 4
                const float* rs = bias + (size_t)b * NTOK;
                const float m0 = gm / __ldg(rs + grow);
                const float m1 = gm / __ldg(rs + grow + 8);
                float* C = (float*)Cout + (size_t)b * sC;
                float* p00 = C + (size_t)gcol * ldc + grow;
                float* p01 = C + (size_t)(gcol + 1) * ldc + grow;
                p00[0] = m0 * d0 + p00[0];
                p01[0] = m0 * d1 + p01[0];
                p00[8] = m1 * d2 + p00[8];
                p01[8] = m1 * d3 + p01[8];
            }
        }
    }
}

// transpose fp32 [b][C][1024] -> bf16 hi(/lo) [b][1024][C]
__global__ __launch_bounds__(256) void transpose_split(
    const float* __restrict__ in, bf16* __restrict__ hi, bf16* __restrict__ lo, int C)
{
    __shared__ float t[32][33];
    const int c0 = blockIdx.x * 32, n0 = blockIdx.y * 32, b = blockIdx.z;
    const float* pin = in + (size_t)b * C * NTOK;
    const int tx = threadIdx.x & 31, ty = threadIdx.x >> 5;
    #pragma unroll
    for (int i = 0; i < 4; i++)
        t[ty + i * 8][tx] = pin[(size_t)(c0 + ty + i * 8) * NTOK + n0 + tx];
    __syncthreads();
    #pragma unroll
    for (int i = 0; i < 4; i++) {
        float x = t[tx][ty + i * 8];
        bf16 h = __float2bfloat16(x);
        size_t o = (size_t)b * NTOK * C + (size_t)(n0 + ty + i * 8) * C + c0 + tx;
        hi[o] = h;
        if (lo) lo[o] = __float2bfloat16(x - __bfloat162float(h));
    }
}

// transpose fp32 [R][C] -> bf16 [C][R]  (weights)
__global__ __launch_bounds__(256) void transpose_w(
    const float* __restrict__ in, bf16* __restrict__ out, int R, int C)
{
    __shared__ float t[32][33];
    const int c0 = blockIdx.x * 32, r0 = blockIdx.y * 32;
    const int tx = threadIdx.x & 31, ty = threadIdx.x >> 5;
    #pragma unroll
    for (int i = 0; i < 4; i++)
        t[ty + i * 8][tx] = in[(size_t)(r0 + ty + i * 8) * C + c0 + tx];
    __syncthreads();
    #pragma unroll
    for (int i = 0; i < 4; i++)
        out[(size_t)(c0 + ty + i * 8) * R + r0 + tx] = __float2bfloat16(t[tx][ty + i * 8]);
}

__global__ void split_bf16(const float* __restrict__ in, bf16* __restrict__ hi,
                           bf16* __restrict__ lo, int n)
{
    int i = blockIdx.x * 256 + threadIdx.x;
    if (i < n) {
        float x = in[i];
        bf16 h = __float2bfloat16(x);
        hi[i] = h;
        if (lo) lo[i] = __float2bfloat16(x - __bfloat162float(h));
    }
}

__global__ void combine_bias2(
    const float* __restrict__ Wq, const float* __restrict__ bcnn, const float* __restrict__ bq,
    const float* __restrict__ Wk, const float* __restrict__ bk,
    const float* __restrict__ Wv, const float* __restrict__ bv,
    const float* __restrict__ beff,
    float* __restrict__ bqc, float* __restrict__ bke, float* __restrict__ bve)
{
    const int which = blockIdx.y;
    const int o = blockIdx.x * 8 + (threadIdx.x >> 5);
    const int l = threadIdx.x & 31;
    const float* W   = (which == 0) ? Wq : (which == 1) ? Wk : Wv;
    const float* vin = (which == 0) ? bcnn : beff;
    const float* add = (which == 0) ? bq : (which == 1) ? bk : bv;
    float s = 0.f;
    for (int c = l; c < HIDC; c += 32) s += W[(size_t)o * HIDC + c] * vin[c];
    #pragma unroll
    for (int d = 16; d; d >>= 1) s += __shfl_xor_sync(0xFFFFFFFFu, s, d);
    if (l == 0) {
        float* dst = (which == 0) ? bqc : (which == 1) ? bke : bve;
        dst[o] = s + add[o];
    }
}

// ------------------------------ launch ------------------------------------
extern "C" void kernel_launch(void* const* d_in, const int* in_sizes, int n_in,
                              void* d_out, int out_size)
{
    const float* xc = (const float*)d_in[0];
    const float* xe = (const float*)d_in[1];
    const float* Wc = (const float*)d_in[2];
    const float* bc = (const float*)d_in[3];
    const float* We = (const float*)d_in[4];
    const float* be = (const float*)d_in[5];
    const float* Wq = (const float*)d_in[6];
    const float* bq = (const float*)d_in[7];
    const float* Wk = (const float*)d_in[8];
    const float* bk = (const float*)d_in[9];
    const float* Wv = (const float*)d_in[10];
    const float* bv = (const float*)d_in[11];
    const float* gamma = (const float*)d_in[12];
    float* out = (float*)d_out;

    float *p_bqc, *p_bke, *p_bve, *p_rsum;
    bf16 *p_Wq_h, *p_Wk_h, *p_Wv_h, *p_WcT, *p_WeT;
    bf16 *p_Wc_h, *p_Wc_l, *p_Wqc_h, *p_Wke_h, *p_Wve_h;
    bf16 *p_XcT_h, *p_XcT_l, *p_XeT_h, *p_qb, *p_kb, *p_vb, *p_P;
    cudaGetSymbolAddress((void**)&p_bqc, g_bqc);
    cudaGetSymbolAddress((void**)&p_bke, g_bke);
    cudaGetSymbolAddress((void**)&p_bve, g_bve);
    cudaGetSymbolAddress((void**)&p_rsum, g_rsum);
    cudaGetSymbolAddress((void**)&p_Wq_h, g_Wq_h);
    cudaGetSymbolAddress((void**)&p_Wk_h, g_Wk_h);
    cudaGetSymbolAddress((void**)&p_Wv_h, g_Wv_h);
    cudaGetSymbolAddress((void**)&p_WcT, g_WcT);
    cudaGetSymbolAddress((void**)&p_WeT, g_WeT);
    cudaGetSymbolAddress((void**)&p_Wc_h, g_Wc_h);
    cudaGetSymbolAddress((void**)&p_Wc_l, g_Wc_l);
    cudaGetSymbolAddress((void**)&p_Wqc_h, g_Wqc_h);
    cudaGetSymbolAddress((void**)&p_Wke_h, g_Wke_h);
    cudaGetSymbolAddress((void**)&p_Wve_h, g_Wve_h);
    cudaGetSymbolAddress((void**)&p_XcT_h, g_XcT_h);
    cudaGetSymbolAddress((void**)&p_XcT_l, g_XcT_l);
    cudaGetSymbolAddress((void**)&p_XeT_h, g_XeT_h);
    cudaGetSymbolAddress((void**)&p_qb, g_qb);
    cudaGetSymbolAddress((void**)&p_kb, g_kb);
    cudaGetSymbolAddress((void**)&p_vb, g_vb);
    cudaGetSymbolAddress((void**)&p_P, g_P);

    const int SM_PLAIN = 40960;
    const int SM_SPLIT = 81920;
    cudaFuncSetAttribute(mma_gemm<true, 1, 0>, cudaFuncAttributeMaxDynamicSharedMemorySize, SM_SPLIT);
    cudaFuncSetAttribute(mma_gemm<false, 0, 1>, cudaFuncAttributeMaxDynamicSharedMemorySize, SM_PLAIN);
    cudaFuncSetAttribute(mma_gemm<false, 2, 1>, cudaFuncAttributeMaxDynamicSharedMemorySize, SM_PLAIN);
    cudaFuncSetAttribute(mma_gemm<false, 1, 1>, cudaFuncAttributeMaxDynamicSharedMemorySize, SM_PLAIN);
    cudaFuncSetAttribute(mma_gemm<false, 0, 3>, cudaFuncAttributeMaxDynamicSharedMemorySize, SM_PLAIN);
    cudaFuncSetAttribute(mma_gemm<false, 0, 4>, cudaFuncAttributeMaxDynamicSharedMemorySize, SM_PLAIN);

    const size_t sXc = (size_t)NTOK * HIDC;
    const size_t sXe = (size_t)NTOK * CEFF;
    const size_t sO  = (size_t)HIDC * NTOK;
    const size_t sAt = (size_t)NTOK * NTOK;

    // weight prep: bf16 casts + transposes
    split_bf16<<<1024, 256>>>(Wq, p_Wq_h, nullptr, HIDC * HIDC);
    split_bf16<<<1024, 256>>>(Wk, p_Wk_h, nullptr, HIDC * HIDC);
    split_bf16<<<1024, 256>>>(Wv, p_Wv_h, nullptr, HIDC * HIDC);
    split_bf16<<<1024, 256>>>(Wc, p_Wc_h, p_Wc_l, HIDC * HIDC);
    transpose_w<<<dim3(16, 16), 256>>>(Wc, p_WcT, HIDC, HIDC);
    transpose_w<<<dim3(40, 16), 256>>>(We, p_WeT, HIDC, CEFF);
    combine_bias2<<<dim3(64, 3), 256>>>(Wq, bc, bq, Wk, bk, Wv, bv, be, p_bqc, p_bke, p_bve);

    // weight folds on tensor cores (bf16 out):
    // Wqc[o][cc] = sum_c Wq[o][c] Wc[c][cc]  (B = WcT)
    mma_gemm<false, 0, 1><<<dim3(4, 4, 1), 256, SM_PLAIN>>>(
        p_Wq_h, nullptr, p_WcT, nullptr, HIDC, HIDC, 0, 0,
        p_Wqc_h, HIDC, 0, nullptr, nullptr, HIDC);
    // Wke[o][ce] = sum_c Wk[o][c] We[c][ce]  (B = WeT)
    mma_gemm<false, 0, 1><<<dim3(10, 4, 1), 256, SM_PLAIN>>>(
        p_Wk_h, nullptr, p_WeT, nullptr, HIDC, HIDC, 0, 0,
        p_Wke_h, CEFF, 0, nullptr, nullptr, HIDC);
    mma_gemm<false, 0, 1><<<dim3(10, 4, 1), 256, SM_PLAIN>>>(
        p_Wv_h, nullptr, p_WeT, nullptr, HIDC, HIDC, 0, 0,
        p_Wve_h, CEFF, 0, nullptr, nullptr, HIDC);

    // activation transposes
    transpose_split<<<dim3(16, 32, BATCH), 256>>>(xc, p_XcT_h, p_XcT_l, HIDC);
    transpose_split<<<dim3(40, 32, BATCH), 256>>>(xe, p_XeT_h, nullptr, CEFF);

    // cnn_proj (split bf16) -> d_out fp32 [b][c][n]
    mma_gemm<true, 1, 0><<<dim3(8, 4, BATCH), 256, SM_SPLIT>>>(
        p_Wc_h, p_Wc_l, p_XcT_h, p_XcT_l, HIDC, HIDC, 0, sXc,
        out, NTOK, sO, bc, nullptr, HIDC);

    // q[b][n][c] bf16
    mma_gemm<false, 2, 1><<<dim3(4, 8, BATCH), 256, SM_PLAIN>>>(
        p_XcT_h, nullptr, p_Wqc_h, nullptr, HIDC, HIDC, sXc, 0,
        p_qb, HIDC, sXc, p_bqc, nullptr, HIDC);

    // k[b][m][c] bf16
    mma_gemm<false, 2, 1><<<dim3(4, 8, BATCH), 256, SM_PLAIN>>>(
        p_XeT_h, nullptr, p_Wke_h, nullptr, CEFF, CEFF, sXe, 0,
        p_kb, HIDC, sXc, p_bke, nullptr, CEFF);

    // v[b][c][m] bf16
    mma_gemm<false, 1, 1><<<dim3(8, 4, BATCH), 256, SM_PLAIN>>>(
        p_Wve_h, nullptr, p_XeT_h, nullptr, CEFF, CEFF, 0, sXe,
        p_vb, NTOK, sO, p_bve, nullptr, CEFF);

    // zero row sums, then fused logits + exp + rowsum -> P (unnormalized)
    cudaMemsetAsync(p_rsum, 0, (size_t)BATCH * NTOK * sizeof(float));
    mma_gemm<false, 0, 3><<<dim3(8, 8, BATCH), 256, SM_PLAIN>>>(
        p_qb, nullptr, p_kb, nullptr, HIDC, HIDC, sXc, sXc,
        p_P, NTOK, sAt, p_rsum, nullptr, HIDC);

    // out[b][c][n] += gamma/rowsum[n] * (P @ v^T)
    mma_gemm<false, 0, 4><<<dim3(4, 8, BATCH), 256, SM_PLAIN>>>(
        p_P, nullptr, p_vb, nullptr, NTOK, NTOK, sAt, sO,
        out, NTOK, sO, p_rsum, gamma, NTOK);
}

// round 7
// speedup vs baseline: 6.0784x; 1.2387x over previous
#include <cuda_runtime.h>
#include <cuda_bf16.h>
#include <cstdint>
#include <cstddef>

#define HIDC 512
#define NTOK 1024
#define BATCH 32
#define CEFF 1280

typedef __nv_bfloat16 bf16;

// ------------------------- scratch ---------------------------------------
__device__ float g_bqc[HIDC], g_bke[HIDC], g_bve[HIDC];
__device__ float g_rsum[(size_t)BATCH * NTOK];

__device__ bf16 g_Wq_h[HIDC * HIDC], g_Wk_h[HIDC * HIDC], g_Wv_h[HIDC * HIDC];
__device__ bf16 g_WcT[HIDC * HIDC];
__device__ bf16 g_WeT[CEFF * HIDC];
__device__ bf16 g_Wc_h[HIDC * HIDC], g_Wc_l[HIDC * HIDC];
__device__ bf16 g_Wqc_h[HIDC * HIDC];
__device__ bf16 g_Wke_h[HIDC * CEFF], g_Wve_h[HIDC * CEFF];

__device__ bf16 g_XcT_h[(size_t)BATCH * NTOK * HIDC];
__device__ bf16 g_XcT_l[(size_t)BATCH * NTOK * HIDC];
__device__ bf16 g_XeT_h[(size_t)BATCH * NTOK * CEFF];

__device__ bf16 g_qb[(size_t)BATCH * NTOK * HIDC];
__device__ bf16 g_kb[(size_t)BATCH * NTOK * HIDC];
__device__ bf16 g_vb[(size_t)BATCH * HIDC * NTOK];
__device__ bf16 g_P[(size_t)BATCH * NTOK * NTOK];

#define MMA_B16(D, A_, B_) \
    asm volatile("mma.sync.aligned.m16n8k16.row.col.f32.bf16.bf16.f32 " \
        "{%0,%1,%2,%3}, {%4,%5,%6,%7}, {%8,%9}, {%0,%1,%2,%3};" \
        : "+f"((D)[0]), "+f"((D)[1]), "+f"((D)[2]), "+f"((D)[3]) \
        : "r"((A_)[0]), "r"((A_)[1]), "r"((A_)[2]), "r"((A_)[3]), \
          "r"((B_)[0]), "r"((B_)[1]))

#define LDSM4(R0, R1, R2, R3, ADDR) \
    asm volatile("ldmatrix.sync.aligned.m8n8.x4.shared.b16 {%0,%1,%2,%3}, [%4];" \
        : "=r"(R0), "=r"(R1), "=r"(R2), "=r"(R3) : "r"(ADDR))

__device__ __forceinline__ uint32_t smem_u32(const void* p) {
    uint32_t a;
    asm("{ .reg .u64 t; cvta.to.shared.u64 t, %1; cvt.u32.u64 %0, t; }" : "=r"(a) : "l"(p));
    return a;
}
__device__ __forceinline__ void cp16(uint32_t dst, const void* src) {
    asm volatile("cp.async.cg.shared.global [%0], [%1], 16;" :: "r"(dst), "l"(src));
}
__device__ __forceinline__ void cp_commit() {
    asm volatile("cp.async.commit_group;" ::: "memory");
}
template<int N> __device__ __forceinline__ void cp_wait() {
    asm volatile("cp.async.wait_group %0;" :: "n"(N) : "memory");
}

// ---------------------------------------------------------------------------
// bf16 HMMA GEMM, 2-stage cp.async pipeline, BK=64, ldmatrix fragments.
// C[M0+128, N0+128] = sum_K A[m,k] * B[n,k]  (both K-major)
// SPLIT adds Ah*Bl + Al*Bh.  BIASM: 0 none, 1 bias[row], 2 bias[col]
// OUTM: 0 fp32 row-major (+bias)
//       1 bf16 row-major (+bias)
//       3 bf16 row-major exp(D) + rowsum atomicAdd into bias
//       4 fp32 row-major RMW: C += gamma/rowsum[col] * D
// smem tile: 128 rows x 72 elems (144 B/row). A@0, B@18432; Al@36864, Bl@55296.
// ---------------------------------------------------------------------------
template<bool SPLIT, int BIASM, int OUTM>
__global__ __launch_bounds__(256) void mma_gemm(
    const bf16* __restrict__ Ah, const bf16* __restrict__ Al,
    const bf16* __restrict__ Bh, const bf16* __restrict__ Bl,
    int lda, int ldb, size_t sA, size_t sB,
    void* __restrict__ Cout, int ldc, size_t sC,
    const float* __restrict__ bias, const float* __restrict__ gamma, int K)
{
    extern __shared__ char dynsm[];
    constexpr int TILE  = 18432;               // 128*72*2
    constexpr int STAGE = SPLIT ? 4 * TILE : 2 * TILE;
    const uint32_t sm0 = smem_u32(dynsm);

    const int tid = threadIdx.x;
    const int wid = tid >> 5;
    const int lid = tid & 31;
    const int wm = wid & 1;
    const int wn = wid >> 1;
    const int g  = lid >> 2;
    const int tc = (lid & 3) * 2;

    const int M0 = blockIdx.y * 128;
    const int N0 = blockIdx.x * 128;
    const int b  = blockIdx.z;

    const bf16* pA = Ah + (size_t)b * sA + (size_t)M0 * lda;
    const bf16* pB = Bh + (size_t)b * sB + (size_t)N0 * ldb;
    const bf16* pAl = SPLIT ? (Al + (size_t)b * sA + (size_t)M0 * lda) : nullptr;
    const bf16* pBl = SPLIT ? (Bl + (size_t)b * sB + (size_t)N0 * ldb) : nullptr;

    const int l8  = lid & 7;
    const int mi1 = (lid >> 3) & 1;
    const int mi2 = (lid >> 4) & 1;
    const uint32_t offA = (uint32_t)(((wm * 64 + mi1 * 8 + l8) * 72 + mi2 * 8) * 2);
    const uint32_t offB = (uint32_t)(((wn * 32 + mi2 * 8 + l8) * 72 + mi1 * 8) * 2);

    float acc[4][4][4];
    #pragma unroll
    for (int i = 0; i < 4; i++)
        #pragma unroll
        for (int j = 0; j < 4; j++)
            #pragma unroll
            for (int r = 0; r < 4; r++) acc[i][j][r] = 0.f;

    const int nk = K >> 6;

    // copy: 128 rows x 64 elems per tile = 1024 16B-chunks; 4 per thread
    auto copy_stage = [&](int buf, int kt) {
        const int k0 = kt << 6;
        const uint32_t sb = sm0 + buf * STAGE;
        #pragma unroll
        for (int s = 0; s < 4; s++) {
            const int i = tid + s * 256;
            const int r = i >> 3, c = (i & 7) * 8;
            const uint32_t so = (uint32_t)((r * 72 + c) * 2);
            cp16(sb + so,        pA + (size_t)r * lda + k0 + c);
            cp16(sb + TILE + so, pB + (size_t)r * ldb + k0 + c);
            if (SPLIT) {
                cp16(sb + 2 * TILE + so, pAl + (size_t)r * lda + k0 + c);
                cp16(sb + 3 * TILE + so, pBl + (size_t)r * ldb + k0 + c);
            }
        }
        cp_commit();
    };

    copy_stage(0, 0);

    for (int kt = 0; kt < nk; kt++) {
        if (kt + 1 < nk) {
            copy_stage((kt + 1) & 1, kt + 1);
            cp_wait<1>();
        } else {
            cp_wait<0>();
        }
        __syncthreads();

        const uint32_t sb = sm0 + (kt & 1) * STAGE;
        #pragma unroll
        for (int ks = 0; ks < 64; ks += 16) {
            uint32_t a[4][4], bb[4][2];
            #pragma unroll
            for (int mt = 0; mt < 4; mt++)
                LDSM4(a[mt][0], a[mt][1], a[mt][2], a[mt][3],
                      sb + offA + mt * 2304 + ks * 2);
            #pragma unroll
            for (int p = 0; p < 2; p++)
                LDSM4(bb[2 * p][0], bb[2 * p][1], bb[2 * p + 1][0], bb[2 * p + 1][1],
                      sb + TILE + offB + p * 2304 + ks * 2);
            #pragma unroll
            for (int mt = 0; mt < 4; mt++)
                #pragma unroll
                for (int nt = 0; nt < 4; nt++)
                    MMA_B16(acc[mt][nt], a[mt], bb[nt]);

            if (SPLIT) {
                uint32_t al[4][4], bl[4][2];
                #pragma unroll
                for (int mt = 0; mt < 4; mt++)
                    LDSM4(al[mt][0], al[mt][1], al[mt][2], al[mt][3],
                          sb + 2 * TILE + offA + mt * 2304 + ks * 2);
                #pragma unroll
                for (int p = 0; p < 2; p++)
                    LDSM4(bl[2 * p][0], bl[2 * p][1], bl[2 * p + 1][0], bl[2 * p + 1][1],
                          sb + 3 * TILE + offB + p * 2304 + ks * 2);
                #pragma unroll
                for (int mt = 0; mt < 4; mt++)
                    #pragma unroll
                    for (int nt = 0; nt < 4; nt++) {
                        MMA_B16(acc[mt][nt], a[mt], bl[nt]);
                        MMA_B16(acc[mt][nt], al[mt], bb[nt]);
                    }
            }
        }
        __syncthreads();
    }

    // ---------------- epilogue ----------------
    if (OUTM == 3) {
        __shared__ float srow[128];
        float* rs = const_cast<float*>(bias) + (size_t)b * NTOK;
        if (tid < 128) srow[tid] = 0.f;
        __syncthreads();
        bf16* C = (bf16*)Cout + (size_t)b * sC;
        #pragma unroll
        for (int mt = 0; mt < 4; mt++) {
            const int grow = M0 + wm * 64 + mt * 16 + g;
            float rp0 = 0.f, rp1 = 0.f;
            #pragma unroll
            for (int nt = 0; nt < 4; nt++) {
                const int gcol = N0 + wn * 32 + nt * 8 + tc;
                float e0 = __expf(acc[mt][nt][0]);
                float e1 = __expf(acc[mt][nt][1]);
                float e2 = __expf(acc[mt][nt][2]);
                float e3 = __expf(acc[mt][nt][3]);
                *(__nv_bfloat162*)(C + (size_t)grow * ldc + gcol) = __floats2bfloat162_rn(e0, e1);
                *(__nv_bfloat162*)(C + (size_t)(grow + 8) * ldc + gcol) = __floats2bfloat162_rn(e2, e3);
                rp0 += e0 + e1;
                rp1 += e2 + e3;
            }
            rp0 += __shfl_xor_sync(0xFFFFFFFFu, rp0, 1);
            rp0 += __shfl_xor_sync(0xFFFFFFFFu, rp0, 2);
            rp1 += __shfl_xor_sync(0xFFFFFFFFu, rp1, 1);
            rp1 += __shfl_xor_sync(0xFFFFFFFFu, rp1, 2);
            if ((lid & 3) == 0) {
                atomicAdd(&srow[wm * 64 + mt * 16 + g], rp0);
                atomicAdd(&srow[wm * 64 + mt * 16 + 8 + g], rp1);
            }
        }
        __syncthreads();
        if (tid < 128) atomicAdd(rs + M0 + tid, srow[tid]);
        return;
    }

    const float gm = (OUTM == 4) ? gamma[0] : 0.f;
    #pragma unroll
    for (int mt = 0; mt < 4; mt++) {
        #pragma unroll
        for (int nt = 0; nt < 4; nt++) {
            const int grow = M0 + wm * 64 + mt * 16 + g;
            const int gcol = N0 + wn * 32 + nt * 8 + tc;
            float d0 = acc[mt][nt][0], d1 = acc[mt][nt][1];
            float d2 = acc[mt][nt][2], d3 = acc[mt][nt][3];

            if (OUTM == 0) {
                float* C = (float*)Cout + (size_t)b * sC;
                if (BIASM == 1) {
                    float br0 = __ldg(bias + grow), br1 = __ldg(bias + grow + 8);
                    d0 += br0; d1 += br0; d2 += br1; d3 += br1;
                } else if (BIASM == 2) {
                    float bc0 = __ldg(bias + gcol), bc1 = __ldg(bias + gcol + 1);
                    d0 += bc0; d1 += bc1; d2 += bc0; d3 += bc1;
                }
                *(float2*)(C + (size_t)grow * ldc + gcol) = make_float2(d0, d1);
                *(float2*)(C + (size_t)(grow + 8) * ldc + gcol) = make_float2(d2, d3);
            } else if (OUTM == 1) {
                bf16* C = (bf16*)Cout + (size_t)b * sC;
                if (BIASM == 1) {
                    float br0 = __ldg(bias + grow), br1 = __ldg(bias + grow + 8);
                    d0 += br0; d1 += br0; d2 += br1; d3 += br1;
                } else if (BIASM == 2) {
                    float bc0 = __ldg(bias + gcol), bc1 = __ldg(bias + gcol + 1);
                    d0 += bc0; d1 += bc1; d2 += bc0; d3 += bc1;
                }
                *(__nv_bfloat162*)(C + (size_t)grow * ldc + gcol) = __floats2bfloat162_rn(d0, d1);
                *(__nv_bfloat162*)(C + (size_t)(grow + 8) * ldc + gcol) = __floats2bfloat162_rn(d2, d3);
            } else { // OUTM == 4: row-major RMW with per-column scale gm/rs[col]
                const float* rs = bias + (size_t)b * NTOK;
                const float s0 = gm / __ldg(rs + gcol);
                const float s1 = gm / __ldg(rs + gcol + 1);
                float* C = (float*)Cout + (size_t)b * sC;
                float2 c0 = *(float2*)(C + (size_t)grow * ldc + gcol);
                float2 c1 = *(float2*)(C + (size_t)(grow + 8) * ldc + gcol);
                c0.x += s0 * d0; c0.y += s1 * d1;
                c1.x += s0 * d2; c1.y += s1 * d3;
                *(float2*)(C + (size_t)grow * ldc + gcol) = c0;
                *(float2*)(C + (size_t)(grow + 8) * ldc + gcol) = c1;
            }
        }
    }
}

// transpose fp32 [b][C][1024] -> bf16 hi(/lo) [b][1024][C]
__global__ __launch_bounds__(256) void transpose_split(
    const float* __restrict__ in, bf16* __restrict__ hi, bf16* __restrict__ lo, int C)
{
    __shared__ float t[32][33];
    const int c0 = blockIdx.x * 32, n0 = blockIdx.y * 32, b = blockIdx.z;
    const float* pin = in + (size_t)b * C * NTOK;
    const int tx = threadIdx.x & 31, ty = threadIdx.x >> 5;
    #pragma unroll
    for (int i = 0; i < 4; i++)
        t[ty + i * 8][tx] = pin[(size_t)(c0 + ty + i * 8) * NTOK + n0 + tx];
    __syncthreads();
    #pragma unroll
    for (int i = 0; i < 4; i++) {
        float x = t[tx][ty + i * 8];
        bf16 h = __float2bfloat16(x);
        size_t o = (size_t)b * NTOK * C + (size_t)(n0 + ty + i * 8) * C + c0 + tx;
        hi[o] = h;
        if (lo) lo[o] = __float2bfloat16(x - __bfloat162float(h));
    }
}

// fused weight transposes: z=0 Wc[512,512]->WcT, z=1 We[512,1280]->WeT
__global__ __launch_bounds__(256) void transpose_w2(
    const float* __restrict__ Wc, bf16* __restrict__ WcT,
    const float* __restrict__ We, bf16* __restrict__ WeT)
{
    const int z = blockIdx.z;
    const float* in = z ? We : Wc;
    bf16* out = z ? WeT : WcT;
    const int C = z ? CEFF : HIDC;
    if (blockIdx.x * 32 >= C) return;
    __shared__ float t[32][33];
    const int c0 = blockIdx.x * 32, r0 = blockIdx.y * 32;
    const int tx = threadIdx.x & 31, ty = threadIdx.x >> 5;
    #pragma unroll
    for (int i = 0; i < 4; i++)
        t[ty + i * 8][tx] = in[(size_t)(r0 + ty + i * 8) * C + c0 + tx];
    __syncthreads();
    #pragma unroll
    for (int i = 0; i < 4; i++)
        out[(size_t)(c0 + ty + i * 8) * HIDC + r0 + tx] = __float2bfloat16(t[tx][ty + i * 8]);
}

// fused weight casts: y=0 Wq, y=1 Wk, y=2 Wv (hi), y=3 Wc (hi+lo)
__global__ void cast_weights(
    const float* __restrict__ Wq, const float* __restrict__ Wk,
    const float* __restrict__ Wv, const float* __restrict__ Wc,
    bf16* __restrict__ oq, bf16* __restrict__ ok, bf16* __restrict__ ov,
    bf16* __restrict__ ch, bf16* __restrict__ cl)
{
    const int i = blockIdx.x * 256 + threadIdx.x;
    const int w = blockIdx.y;
    if (w == 0)      oq[i] = __float2bfloat16(Wq[i]);
    else if (w == 1) ok[i] = __float2bfloat16(Wk[i]);
    else if (w == 2) ov[i] = __float2bfloat16(Wv[i]);
    else {
        float x = Wc[i];
        bf16 h = __float2bfloat16(x);
        ch[i] = h;
        cl[i] = __float2bfloat16(x - __bfloat162float(h));
    }
}

__global__ void combine_bias2(
    const float* __restrict__ Wq, const float* __restrict__ bcnn, const float* __restrict__ bq,
    const float* __restrict__ Wk, const float* __restrict__ bk,
    const float* __restrict__ Wv, const float* __restrict__ bv,
    const float* __restrict__ beff,
    float* __restrict__ bqc, float* __restrict__ bke, float* __restrict__ bve)
{
    const int which = blockIdx.y;
    const int o = blockIdx.x * 8 + (threadIdx.x >> 5);
    const int l = threadIdx.x & 31;
    const float* W   = (which == 0) ? Wq : (which == 1) ? Wk : Wv;
    const float* vin = (which == 0) ? bcnn : beff;
    const float* add = (which == 0) ? bq : (which == 1) ? bk : bv;
    float s = 0.f;
    for (int c = l; c < HIDC; c += 32) s += W[(size_t)o * HIDC + c] * vin[c];
    #pragma unroll
    for (int d = 16; d; d >>= 1) s += __shfl_xor_sync(0xFFFFFFFFu, s, d);
    if (l == 0) {
        float* dst = (which == 0) ? bqc : (which == 1) ? bke : bve;
        dst[o] = s + add[o];
    }
}

// ------------------------------ launch ------------------------------------
extern "C" void kernel_launch(void* const* d_in, const int* in_sizes, int n_in,
                              void* d_out, int out_size)
{
    const float* xc = (const float*)d_in[0];
    const float* xe = (const float*)d_in[1];
    const float* Wc = (const float*)d_in[2];
    const float* bc = (const float*)d_in[3];
    const float* We = (const float*)d_in[4];
    const float* be = (const float*)d_in[5];
    const float* Wq = (const float*)d_in[6];
    const float* bq = (const float*)d_in[7];
    const float* Wk = (const float*)d_in[8];
    const float* bk = (const float*)d_in[9];
    const float* Wv = (const float*)d_in[10];
    const float* bv = (const float*)d_in[11];
    const float* gamma = (const float*)d_in[12];
    float* out = (float*)d_out;

    float *p_bqc, *p_bke, *p_bve, *p_rsum;
    bf16 *p_Wq_h, *p_Wk_h, *p_Wv_h, *p_WcT, *p_WeT;
    bf16 *p_Wc_h, *p_Wc_l, *p_Wqc_h, *p_Wke_h, *p_Wve_h;
    bf16 *p_XcT_h, *p_XcT_l, *p_XeT_h, *p_qb, *p_kb, *p_vb, *p_P;
    cudaGetSymbolAddress((void**)&p_bqc, g_bqc);
    cudaGetSymbolAddress((void**)&p_bke, g_bke);
    cudaGetSymbolAddress((void**)&p_bve, g_bve);
    cudaGetSymbolAddress((void**)&p_rsum, g_rsum);
    cudaGetSymbolAddress((void**)&p_Wq_h, g_Wq_h);
    cudaGetSymbolAddress((void**)&p_Wk_h, g_Wk_h);
    cudaGetSymbolAddress((void**)&p_Wv_h, g_Wv_h);
    cudaGetSymbolAddress((void**)&p_WcT, g_WcT);
    cudaGetSymbolAddress((void**)&p_WeT, g_WeT);
    cudaGetSymbolAddress((void**)&p_Wc_h, g_Wc_h);
    cudaGetSymbolAddress((void**)&p_Wc_l, g_Wc_l);
    cudaGetSymbolAddress((void**)&p_Wqc_h, g_Wqc_h);
    cudaGetSymbolAddress((void**)&p_Wke_h, g_Wke_h);
    cudaGetSymbolAddress((void**)&p_Wve_h, g_Wve_h);
    cudaGetSymbolAddress((void**)&p_XcT_h, g_XcT_h);
    cudaGetSymbolAddress((void**)&p_XcT_l, g_XcT_l);
    cudaGetSymbolAddress((void**)&p_XeT_h, g_XeT_h);
    cudaGetSymbolAddress((void**)&p_qb, g_qb);
    cudaGetSymbolAddress((void**)&p_kb, g_kb);
    cudaGetSymbolAddress((void**)&p_vb, g_vb);
    cudaGetSymbolAddress((void**)&p_P, g_P);

    const int SM_PLAIN = 73728;    // 2 stages x 2 tiles x 18432
    const int SM_SPLIT = 147456;   // 2 stages x 4 tiles x 18432
    cudaFuncSetAttribute(mma_gemm<true, 1, 0>, cudaFuncAttributeMaxDynamicSharedMemorySize, SM_SPLIT);
    cudaFuncSetAttribute(mma_gemm<false, 0, 1>, cudaFuncAttributeMaxDynamicSharedMemorySize, SM_PLAIN);
    cudaFuncSetAttribute(mma_gemm<false, 2, 1>, cudaFuncAttributeMaxDynamicSharedMemorySize, SM_PLAIN);
    cudaFuncSetAttribute(mma_gemm<false, 1, 1>, cudaFuncAttributeMaxDynamicSharedMemorySize, SM_PLAIN);
    cudaFuncSetAttribute(mma_gemm<false, 0, 3>, cudaFuncAttributeMaxDynamicSharedMemorySize, SM_PLAIN);
    cudaFuncSetAttribute(mma_gemm<false, 0, 4>, cudaFuncAttributeMaxDynamicSharedMemorySize, SM_PLAIN);

    const size_t sXc = (size_t)NTOK * HIDC;
    const size_t sXe = (size_t)NTOK * CEFF;
    const size_t sO  = (size_t)HIDC * NTOK;
    const size_t sAt = (size_t)NTOK * NTOK;

    // fused weight prep
    cast_weights<<<dim3(1024, 4), 256>>>(Wq, Wk, Wv, Wc, p_Wq_h, p_Wk_h, p_Wv_h, p_Wc_h, p_Wc_l);
    transpose_w2<<<dim3(40, 16, 2), 256>>>(Wc, p_WcT, We, p_WeT);
    combine_bias2<<<dim3(64, 3), 256>>>(Wq, bc, bq, Wk, bk, Wv, bv, be, p_bqc, p_bke, p_bve);

    // weight folds on tensor cores
    mma_gemm<false, 0, 1><<<dim3(4, 4, 1), 256, SM_PLAIN>>>(
        p_Wq_h, nullptr, p_WcT, nullptr, HIDC, HIDC, 0, 0,
        p_Wqc_h, HIDC, 0, nullptr, nullptr, HIDC);
    mma_gemm<false, 0, 1><<<dim3(10, 4, 1), 256, SM_PLAIN>>>(
        p_Wk_h, nullptr, p_WeT, nullptr, HIDC, HIDC, 0, 0,
        p_Wke_h, CEFF, 0, nullptr, nullptr, HIDC);
    mma_gemm<false, 0, 1><<<dim3(10, 4, 1), 256, SM_PLAIN>>>(
        p_Wv_h, nullptr, p_WeT, nullptr, HIDC, HIDC, 0, 0,
        p_Wve_h, CEFF, 0, nullptr, nullptr, HIDC);

    // activation transposes
    transpose_split<<<dim3(16, 32, BATCH), 256>>>(xc, p_XcT_h, p_XcT_l, HIDC);
    transpose_split<<<dim3(40, 32, BATCH), 256>>>(xe, p_XeT_h, nullptr, CEFF);

    // cnn_proj (split bf16) -> d_out fp32 [b][c][n]
    mma_gemm<true, 1, 0><<<dim3(8, 4, BATCH), 256, SM_SPLIT>>>(
        p_Wc_h, p_Wc_l, p_XcT_h, p_XcT_l, HIDC, HIDC, 0, sXc,
        out, NTOK, sO, bc, nullptr, HIDC);

    // q[b][n][c]
    mma_gemm<false, 2, 1><<<dim3(4, 8, BATCH), 256, SM_PLAIN>>>(
        p_XcT_h, nullptr, p_Wqc_h, nullptr, HIDC, HIDC, sXc, 0,
        p_qb, HIDC, sXc, p_bqc, nullptr, HIDC);

    // k[b][m][c]
    mma_gemm<false, 2, 1><<<dim3(4, 8, BATCH), 256, SM_PLAIN>>>(
        p_XeT_h, nullptr, p_Wke_h, nullptr, CEFF, CEFF, sXe, 0,
        p_kb, HIDC, sXc, p_bke, nullptr, CEFF);

    // v[b][c][m]
    mma_gemm<false, 1, 1><<<dim3(8, 4, BATCH), 256, SM_PLAIN>>>(
        p_Wve_h, nullptr, p_XeT_h, nullptr, CEFF, CEFF, 0, sXe,
        p_vb, NTOK, sO, p_bve, nullptr, CEFF);

    // fused logits + exp + rowsum -> P (unnormalized)
    cudaMemsetAsync(p_rsum, 0, (size_t)BATCH * NTOK * sizeof(float));
    mma_gemm<false, 0, 3><<<dim3(8, 8, BATCH), 256, SM_PLAIN>>>(
        p_qb, nullptr, p_kb, nullptr, HIDC, HIDC, sXc, sXc,
        p_P, NTOK, sAt, p_rsum, nullptr, HIDC);

    // out[b][c][n] += gamma/rowsum[n] * (v @ P^T)   -- coalesced row-major RMW
    mma_gemm<false, 0, 4><<<dim3(8, 4, BATCH), 256, SM_PLAIN>>>(
        p_vb, nullptr, p_P, nullptr, NTOK, NTOK, sO, sAt,
        out, NTOK, sO, p_rsum, gamma, NTOK);
}

// round 8
// speedup vs baseline: 6.2830x; 1.0336x over previous
#include <cuda_runtime.h>
#include <cuda_bf16.h>
#include <cstdint>
#include <cstddef>

#define HIDC 512
#define NTOK 1024
#define BATCH 32
#define CEFF 1280

typedef __nv_bfloat16 bf16;

// ------------------------- scratch ---------------------------------------
__device__ float g_bqc[HIDC];
__device__ float g_rsum[(size_t)BATCH * NTOK];

__device__ bf16 g_Wq_h[HIDC * HIDC], g_Wk_h[HIDC * HIDC], g_Wv_h[HIDC * HIDC];
__device__ bf16 g_We_h[HIDC * CEFF];
__device__ bf16 g_WcT[HIDC * HIDC];
__device__ bf16 g_Wc_h[HIDC * HIDC], g_Wc_l[HIDC * HIDC];
__device__ bf16 g_Wqc_h[HIDC * HIDC];

__device__ bf16 g_XcT_h[(size_t)BATCH * NTOK * HIDC];
__device__ bf16 g_XcT_l[(size_t)BATCH * NTOK * HIDC];
__device__ bf16 g_XeT_h[(size_t)BATCH * NTOK * CEFF];

__device__ bf16 g_eff[(size_t)BATCH * NTOK * HIDC];   // [b][n][hid] token-major
__device__ bf16 g_qb[(size_t)BATCH * NTOK * HIDC];    // [b][n][c]
__device__ bf16 g_kb[(size_t)BATCH * NTOK * HIDC];    // [b][m][c]
__device__ bf16 g_vb[(size_t)BATCH * HIDC * NTOK];    // [b][c][m]
__device__ bf16 g_P[(size_t)BATCH * NTOK * NTOK];     // [b][n][m] unnormalized exp

#define MMA_B16(D, A_, B_) \
    asm volatile("mma.sync.aligned.m16n8k16.row.col.f32.bf16.bf16.f32 " \
        "{%0,%1,%2,%3}, {%4,%5,%6,%7}, {%8,%9}, {%0,%1,%2,%3};" \
        : "+f"((D)[0]), "+f"((D)[1]), "+f"((D)[2]), "+f"((D)[3]) \
        : "r"((A_)[0]), "r"((A_)[1]), "r"((A_)[2]), "r"((A_)[3]), \
          "r"((B_)[0]), "r"((B_)[1]))

#define LDSM4(R0, R1, R2, R3, ADDR) \
    asm volatile("ldmatrix.sync.aligned.m8n8.x4.shared.b16 {%0,%1,%2,%3}, [%4];" \
        : "=r"(R0), "=r"(R1), "=r"(R2), "=r"(R3) : "r"(ADDR))

__device__ __forceinline__ uint32_t smem_u32(const void* p) {
    uint32_t a;
    asm("{ .reg .u64 t; cvta.to.shared.u64 t, %1; cvt.u32.u64 %0, t; }" : "=r"(a) : "l"(p));
    return a;
}
__device__ __forceinline__ void cp16(uint32_t dst, const void* src) {
    asm volatile("cp.async.cg.shared.global [%0], [%1], 16;" :: "r"(dst), "l"(src));
}
__device__ __forceinline__ void cp_commit() {
    asm volatile("cp.async.commit_group;" ::: "memory");
}
template<int N> __device__ __forceinline__ void cp_wait() {
    asm volatile("cp.async.wait_group %0;" :: "n"(N) : "memory");
}

// ---------------------------------------------------------------------------
// bf16 HMMA GEMM, 2-stage cp.async pipeline, BK=64, ldmatrix fragments.
// C[M0+128, N0+128] = sum_K A[m,k] * B[n,k]  (both K-major)
// SPLIT adds Ah*Bl + Al*Bh.  BIASM: 0 none, 1 bias[row], 2 bias[col]
// OUTM: 0 fp32 row-major (+bias)
//       1 bf16 row-major (+bias)
//       3 bf16 row-major exp(D) + rowsum atomicAdd into bias
//       4 fp32 row-major RMW: C += gamma/rowsum[col] * D
// smem tile: 128 rows x 72 elems. A@0, B@18432; Al@36864, Bl@55296.
// ---------------------------------------------------------------------------
template<bool SPLIT, int BIASM, int OUTM>
__global__ __launch_bounds__(256) void mma_gemm(
    const bf16* __restrict__ Ah, const bf16* __restrict__ Al,
    const bf16* __restrict__ Bh, const bf16* __restrict__ Bl,
    int lda, int ldb, size_t sA, size_t sB,
    void* __restrict__ Cout, int ldc, size_t sC,
    const float* __restrict__ bias, const float* __restrict__ gamma, int K)
{
    extern __shared__ char dynsm[];
    constexpr int TILE  = 18432;
    constexpr int STAGE = SPLIT ? 4 * TILE : 2 * TILE;
    const uint32_t sm0 = smem_u32(dynsm);

    const int tid = threadIdx.x;
    const int wid = tid >> 5;
    const int lid = tid & 31;
    const int wm = wid & 1;
    const int wn = wid >> 1;
    const int g  = lid >> 2;
    const int tc = (lid & 3) * 2;

    const int M0 = blockIdx.y * 128;
    const int N0 = blockIdx.x * 128;
    const int b  = blockIdx.z;

    const bf16* pA = Ah + (size_t)b * sA + (size_t)M0 * lda;
    const bf16* pB = Bh + (size_t)b * sB + (size_t)N0 * ldb;
    const bf16* pAl = SPLIT ? (Al + (size_t)b * sA + (size_t)M0 * lda) : nullptr;
    const bf16* pBl = SPLIT ? (Bl + (size_t)b * sB + (size_t)N0 * ldb) : nullptr;

    const int l8  = lid & 7;
    const int mi1 = (lid >> 3) & 1;
    const int mi2 = (lid >> 4) & 1;
    const uint32_t offA = (uint32_t)(((wm * 64 + mi1 * 8 + l8) * 72 + mi2 * 8) * 2);
    const uint32_t offB = (uint32_t)(((wn * 32 + mi2 * 8 + l8) * 72 + mi1 * 8) * 2);

    float acc[4][4][4];
    #pragma unroll
    for (int i = 0; i < 4; i++)
        #pragma unroll
        for (int j = 0; j < 4; j++)
            #pragma unroll
            for (int r = 0; r < 4; r++) acc[i][j][r] = 0.f;

    const int nk = K >> 6;

    auto copy_stage = [&](int buf, int kt) {
        const int k0 = kt << 6;
        const uint32_t sb = sm0 + buf * STAGE;
        #pragma unroll
        for (int s = 0; s < 4; s++) {
            const int i = tid + s * 256;
            const int r = i >> 3, c = (i & 7) * 8;
            const uint32_t so = (uint32_t)((r * 72 + c) * 2);
            cp16(sb + so,        pA + (size_t)r * lda + k0 + c);
            cp16(sb + TILE + so, pB + (size_t)r * ldb + k0 + c);
            if (SPLIT) {
                cp16(sb + 2 * TILE + so, pAl + (size_t)r * lda + k0 + c);
                cp16(sb + 3 * TILE + so, pBl + (size_t)r * ldb + k0 + c);
            }
        }
        cp_commit();
    };

    copy_stage(0, 0);

    for (int kt = 0; kt < nk; kt++) {
        if (kt + 1 < nk) {
            copy_stage((kt + 1) & 1, kt + 1);
            cp_wait<1>();
        } else {
            cp_wait<0>();
        }
        __syncthreads();

        const uint32_t sb = sm0 + (kt & 1) * STAGE;
        #pragma unroll
        for (int ks = 0; ks < 64; ks += 16) {
            uint32_t a[4][4], bb[4][2];
            #pragma unroll
            for (int mt = 0; mt < 4; mt++)
                LDSM4(a[mt][0], a[mt][1], a[mt][2], a[mt][3],
                      sb + offA + mt * 2304 + ks * 2);
            #pragma unroll
            for (int p = 0; p < 2; p++)
                LDSM4(bb[2 * p][0], bb[2 * p][1], bb[2 * p + 1][0], bb[2 * p + 1][1],
                      sb + TILE + offB + p * 2304 + ks * 2);
            #pragma unroll
            for (int mt = 0; mt < 4; mt++)
                #pragma unroll
                for (int nt = 0; nt < 4; nt++)
                    MMA_B16(acc[mt][nt], a[mt], bb[nt]);

            if (SPLIT) {
                uint32_t al[4][4], bl[4][2];
                #pragma unroll
                for (int mt = 0; mt < 4; mt++)
                    LDSM4(al[mt][0], al[mt][1], al[mt][2], al[mt][3],
                          sb + 2 * TILE + offA + mt * 2304 + ks * 2);
                #pragma unroll
                for (int p = 0; p < 2; p++)
                    LDSM4(bl[2 * p][0], bl[2 * p][1], bl[2 * p + 1][0], bl[2 * p + 1][1],
                          sb + 3 * TILE + offB + p * 2304 + ks * 2);
                #pragma unroll
                for (int mt = 0; mt < 4; mt++)
                    #pragma unroll
                    for (int nt = 0; nt < 4; nt++) {
                        MMA_B16(acc[mt][nt], a[mt], bl[nt]);
                        MMA_B16(acc[mt][nt], al[mt], bb[nt]);
                    }
            }
        }
        __syncthreads();
    }

    // ---------------- epilogue ----------------
    if (OUTM == 3) {
        __shared__ float srow[128];
        float* rs = const_cast<float*>(bias) + (size_t)b * NTOK;
        if (tid < 128) srow[tid] = 0.f;
        __syncthreads();
        bf16* C = (bf16*)Cout + (size_t)b * sC;
        #pragma unroll
        for (int mt = 0; mt < 4; mt++) {
            const int grow = M0 + wm * 64 + mt * 16 + g;
            float rp0 = 0.f, rp1 = 0.f;
            #pragma unroll
            for (int nt = 0; nt < 4; nt++) {
                const int gcol = N0 + wn * 32 + nt * 8 + tc;
                float e0 = __expf(acc[mt][nt][0]);
                float e1 = __expf(acc[mt][nt][1]);
                float e2 = __expf(acc[mt][nt][2]);
                float e3 = __expf(acc[mt][nt][3]);
                *(__nv_bfloat162*)(C + (size_t)grow * ldc + gcol) = __floats2bfloat162_rn(e0, e1);
                *(__nv_bfloat162*)(C + (size_t)(grow + 8) * ldc + gcol) = __floats2bfloat162_rn(e2, e3);
                rp0 += e0 + e1;
                rp1 += e2 + e3;
            }
            rp0 += __shfl_xor_sync(0xFFFFFFFFu, rp0, 1);
            rp0 += __shfl_xor_sync(0xFFFFFFFFu, rp0, 2);
            rp1 += __shfl_xor_sync(0xFFFFFFFFu, rp1, 1);
            rp1 += __shfl_xor_sync(0xFFFFFFFFu, rp1, 2);
            if ((lid & 3) == 0) {
                atomicAdd(&srow[wm * 64 + mt * 16 + g], rp0);
                atomicAdd(&srow[wm * 64 + mt * 16 + 8 + g], rp1);
            }
        }
        __syncthreads();
        if (tid < 128) atomicAdd(rs + M0 + tid, srow[tid]);
        return;
    }

    const float gm = (OUTM == 4) ? gamma[0] : 0.f;
    #pragma unroll
    for (int mt = 0; mt < 4; mt++) {
        #pragma unroll
        for (int nt = 0; nt < 4; nt++) {
            const int grow = M0 + wm * 64 + mt * 16 + g;
            const int gcol = N0 + wn * 32 + nt * 8 + tc;
            float d0 = acc[mt][nt][0], d1 = acc[mt][nt][1];
            float d2 = acc[mt][nt][2], d3 = acc[mt][nt][3];

            if (OUTM == 0) {
                float* C = (float*)Cout + (size_t)b * sC;
                if (BIASM == 1) {
                    float br0 = __ldg(bias + grow), br1 = __ldg(bias + grow + 8);
                    d0 += br0; d1 += br0; d2 += br1; d3 += br1;
                } else if (BIASM == 2) {
                    float bc0 = __ldg(bias + gcol), bc1 = __ldg(bias + gcol + 1);
                    d0 += bc0; d1 += bc1; d2 += bc0; d3 += bc1;
                }
                *(float2*)(C + (size_t)grow * ldc + gcol) = make_float2(d0, d1);
                *(float2*)(C + (size_t)(grow + 8) * ldc + gcol) = make_float2(d2, d3);
            } else if (OUTM == 1) {
                bf16* C = (bf16*)Cout + (size_t)b * sC;
                if (BIASM == 1) {
                    float br0 = __ldg(bias + grow), br1 = __ldg(bias + grow + 8);
                    d0 += br0; d1 += br0; d2 += br1; d3 += br1;
                } else if (BIASM == 2) {
                    float bc0 = __ldg(bias + gcol), bc1 = __ldg(bias + gcol + 1);
                    d0 += bc0; d1 += bc1; d2 += bc0; d3 += bc1;
                }
                *(__nv_bfloat162*)(C + (size_t)grow * ldc + gcol) = __floats2bfloat162_rn(d0, d1);
                *(__nv_bfloat162*)(C + (size_t)(grow + 8) * ldc + gcol) = __floats2bfloat162_rn(d2, d3);
            } else { // OUTM == 4
                const float* rs = bias + (size_t)b * NTOK;
                const float s0 = gm / __ldg(rs + gcol);
                const float s1 = gm / __ldg(rs + gcol + 1);
                float* C = (float*)Cout + (size_t)b * sC;
                float2 c0 = *(float2*)(C + (size_t)grow * ldc + gcol);
                float2 c1 = *(float2*)(C + (size_t)(grow + 8) * ldc + gcol);
                c0.x += s0 * d0; c0.y += s1 * d1;
                c1.x += s0 * d2; c1.y += s1 * d3;
                *(float2*)(C + (size_t)grow * ldc + gcol) = c0;
                *(float2*)(C + (size_t)(grow + 8) * ldc + gcol) = c1;
            }
        }
    }
}

// transpose fp32 [b][C][1024] -> bf16 hi(/lo) [b][1024][C]
__global__ __launch_bounds__(256) void transpose_split(
    const float* __restrict__ in, bf16* __restrict__ hi, bf16* __restrict__ lo, int C)
{
    __shared__ float t[32][33];
    const int c0 = blockIdx.x * 32, n0 = blockIdx.y * 32, b = blockIdx.z;
    const float* pin = in + (size_t)b * C * NTOK;
    const int tx = threadIdx.x & 31, ty = threadIdx.x >> 5;
    #pragma unroll
    for (int i = 0; i < 4; i++)
        t[ty + i * 8][tx] = pin[(size_t)(c0 + ty + i * 8) * NTOK + n0 + tx];
    __syncthreads();
    #pragma unroll
    for (int i = 0; i < 4; i++) {
        float x = t[tx][ty + i * 8];
        bf16 h = __float2bfloat16(x);
        size_t o = (size_t)b * NTOK * C + (size_t)(n0 + ty + i * 8) * C + c0 + tx;
        hi[o] = h;
        if (lo) lo[o] = __float2bfloat16(x - __bfloat162float(h));
    }
}

// Wc [512,512] fp32 -> WcT bf16
__global__ __launch_bounds__(256) void transpose_wc(
    const float* __restrict__ Wc, bf16* __restrict__ WcT)
{
    __shared__ float t[32][33];
    const int c0 = blockIdx.x * 32, r0 = blockIdx.y * 32;
    const int tx = threadIdx.x & 31, ty = threadIdx.x >> 5;
    #pragma unroll
    for (int i = 0; i < 4; i++)
        t[ty + i * 8][tx] = Wc[(size_t)(r0 + ty + i * 8) * HIDC + c0 + tx];
    __syncthreads();
    #pragma unroll
    for (int i = 0; i < 4; i++)
        WcT[(size_t)(c0 + ty + i * 8) * HIDC + r0 + tx] = __float2bfloat16(t[tx][ty + i * 8]);
}

// fused weight casts: y=0 Wq, y=1 Wk, y=2 Wv, y=3 Wc(hi+lo), y=4 We
__global__ void cast_weights(
    const float* __restrict__ Wq, const float* __restrict__ Wk,
    const float* __restrict__ Wv, const float* __restrict__ Wc,
    const float* __restrict__ We,
    bf16* __restrict__ oq, bf16* __restrict__ ok, bf16* __restrict__ ov,
    bf16* __restrict__ ch, bf16* __restrict__ cl, bf16* __restrict__ oe)
{
    const int i = blockIdx.x * 256 + threadIdx.x;
    const int w = blockIdx.y;
    if (w == 4) {
        if (i < HIDC * CEFF) oe[i] = __float2bfloat16(We[i]);
        return;
    }
    if (i >= HIDC * HIDC) return;
    if (w == 0)      oq[i] = __float2bfloat16(Wq[i]);
    else if (w == 1) ok[i] = __float2bfloat16(Wk[i]);
    else if (w == 2) ov[i] = __float2bfloat16(Wv[i]);
    else {
        float x = Wc[i];
        bf16 h = __float2bfloat16(x);
        ch[i] = h;
        cl[i] = __float2bfloat16(x - __bfloat162float(h));
    }
}

// combined q bias: bqc = Wq @ bc + bq
__global__ void combine_qbias(
    const float* __restrict__ Wq, const float* __restrict__ bcnn,
    const float* __restrict__ bq, float* __restrict__ bqc)
{
    const int o = blockIdx.x * 8 + (threadIdx.x >> 5);
    const int l = threadIdx.x & 31;
    float s = 0.f;
    for (int c = l; c < HIDC; c += 32) s += Wq[(size_t)o * HIDC + c] * bcnn[c];
    #pragma unroll
    for (int d = 16; d; d >>= 1) s += __shfl_xor_sync(0xFFFFFFFFu, s, d);
    if (l == 0) bqc[o] = s + bq[o];
}

// ------------------------------ launch ------------------------------------
extern "C" void kernel_launch(void* const* d_in, const int* in_sizes, int n_in,
                              void* d_out, int out_size)
{
    const float* xc = (const float*)d_in[0];
    const float* xe = (const float*)d_in[1];
    const float* Wc = (const float*)d_in[2];
    const float* bc = (const float*)d_in[3];
    const float* We = (const float*)d_in[4];
    const float* be = (const float*)d_in[5];
    const float* Wq = (const float*)d_in[6];
    const float* bq = (const float*)d_in[7];
    const float* Wk = (const float*)d_in[8];
    const float* bk = (const float*)d_in[9];
    const float* Wv = (const float*)d_in[10];
    const float* bv = (const float*)d_in[11];
    const float* gamma = (const float*)d_in[12];
    float* out = (float*)d_out;

    float *p_bqc, *p_rsum;
    bf16 *p_Wq_h, *p_Wk_h, *p_Wv_h, *p_We_h, *p_WcT, *p_Wc_h, *p_Wc_l, *p_Wqc_h;
    bf16 *p_XcT_h, *p_XcT_l, *p_XeT_h, *p_eff, *p_qb, *p_kb, *p_vb, *p_P;
    cudaGetSymbolAddress((void**)&p_bqc, g_bqc);
    cudaGetSymbolAddress((void**)&p_rsum, g_rsum);
    cudaGetSymbolAddress((void**)&p_Wq_h, g_Wq_h);
    cudaGetSymbolAddress((void**)&p_Wk_h, g_Wk_h);
    cudaGetSymbolAddress((void**)&p_Wv_h, g_Wv_h);
    cudaGetSymbolAddress((void**)&p_We_h, g_We_h);
    cudaGetSymbolAddress((void**)&p_WcT, g_WcT);
    cudaGetSymbolAddress((void**)&p_Wc_h, g_Wc_h);
    cudaGetSymbolAddress((void**)&p_Wc_l, g_Wc_l);
    cudaGetSymbolAddress((void**)&p_Wqc_h, g_Wqc_h);
    cudaGetSymbolAddress((void**)&p_XcT_h, g_XcT_h);
    cudaGetSymbolAddress((void**)&p_XcT_l, g_XcT_l);
    cudaGetSymbolAddress((void**)&p_XeT_h, g_XeT_h);
    cudaGetSymbolAddress((void**)&p_eff, g_eff);
    cudaGetSymbolAddress((void**)&p_qb, g_qb);
    cudaGetSymbolAddress((void**)&p_kb, g_kb);
    cudaGetSymbolAddress((void**)&p_vb, g_vb);
    cudaGetSymbolAddress((void**)&p_P, g_P);

    const int SM_PLAIN = 73728;
    const int SM_SPLIT = 147456;
    cudaFuncSetAttribute(mma_gemm<true, 1, 0>, cudaFuncAttributeMaxDynamicSharedMemorySize, SM_SPLIT);
    cudaFuncSetAttribute(mma_gemm<false, 0, 1>, cudaFuncAttributeMaxDynamicSharedMemorySize, SM_PLAIN);
    cudaFuncSetAttribute(mma_gemm<false, 2, 1>, cudaFuncAttributeMaxDynamicSharedMemorySize, SM_PLAIN);
    cudaFuncSetAttribute(mma_gemm<false, 1, 1>, cudaFuncAttributeMaxDynamicSharedMemorySize, SM_PLAIN);
    cudaFuncSetAttribute(mma_gemm<false, 0, 3>, cudaFuncAttributeMaxDynamicSharedMemorySize, SM_PLAIN);
    cudaFuncSetAttribute(mma_gemm<false, 0, 4>, cudaFuncAttributeMaxDynamicSharedMemorySize, SM_PLAIN);

    const size_t sXc = (size_t)NTOK * HIDC;
    const size_t sXe = (size_t)NTOK * CEFF;
    const size_t sO  = (size_t)HIDC * NTOK;
    const size_t sAt = (size_t)NTOK * NTOK;

    // prep
    cast_weights<<<dim3(2560, 5), 256>>>(Wq, Wk, Wv, Wc, We,
        p_Wq_h, p_Wk_h, p_Wv_h, p_Wc_h, p_Wc_l, p_We_h);
    transpose_wc<<<dim3(16, 16), 256>>>(Wc, p_WcT);
    combine_qbias<<<64, 256>>>(Wq, bc, bq, p_bqc);

    // fold Wqc = Wq @ Wc (q path only)
    mma_gemm<false, 0, 1><<<dim3(4, 4, 1), 256, SM_PLAIN>>>(
        p_Wq_h, nullptr, p_WcT, nullptr, HIDC, HIDC, 0, 0,
        p_Wqc_h, HIDC, 0, nullptr, nullptr, HIDC);

    // activation transposes
    transpose_split<<<dim3(16, 32, BATCH), 256>>>(xc, p_XcT_h, p_XcT_l, HIDC);
    transpose_split<<<dim3(40, 32, BATCH), 256>>>(xe, p_XeT_h, nullptr, CEFF);

    // cnn_proj (split bf16) -> d_out fp32 [b][c][n]
    mma_gemm<true, 1, 0><<<dim3(8, 4, BATCH), 256, SM_SPLIT>>>(
        p_Wc_h, p_Wc_l, p_XcT_h, p_XcT_l, HIDC, HIDC, 0, sXc,
        out, NTOK, sO, bc, nullptr, HIDC);

    // q[b][n][c] = XcT @ Wqc^T + bqc
    mma_gemm<false, 2, 1><<<dim3(4, 8, BATCH), 256, SM_PLAIN>>>(
        p_XcT_h, nullptr, p_Wqc_h, nullptr, HIDC, HIDC, sXc, 0,
        p_qb, HIDC, sXc, p_bqc, nullptr, HIDC);

    // eff[b][n][hid] = XeT @ We^T + be   (2-step k/v, step 1)
    mma_gemm<false, 2, 1><<<dim3(4, 8, BATCH), 256, SM_PLAIN>>>(
        p_XeT_h, nullptr, p_We_h, nullptr, CEFF, CEFF, sXe, 0,
        p_eff, HIDC, sXc, be, nullptr, CEFF);

    // k[b][m][c] = eff @ Wk^T + bk
    mma_gemm<false, 2, 1><<<dim3(4, 8, BATCH), 256, SM_PLAIN>>>(
        p_eff, nullptr, p_Wk_h, nullptr, HIDC, HIDC, sXc, 0,
        p_kb, HIDC, sXc, bk, nullptr, HIDC);

    // v[b][c][m] = Wv @ eff^T + bv
    mma_gemm<false, 1, 1><<<dim3(8, 4, BATCH), 256, SM_PLAIN>>>(
        p_Wv_h, nullptr, p_eff, nullptr, HIDC, HIDC, 0, sXc,
        p_vb, NTOK, sO, bv, nullptr, HIDC);

    // fused logits + exp + rowsum -> P (unnormalized)
    cudaMemsetAsync(p_rsum, 0, (size_t)BATCH * NTOK * sizeof(float));
    mma_gemm<false, 0, 3><<<dim3(8, 8, BATCH), 256, SM_PLAIN>>>(
        p_qb, nullptr, p_kb, nullptr, HIDC, HIDC, sXc, sXc,
        p_P, NTOK, sAt, p_rsum, nullptr, HIDC);

    // out[b][c][n] += gamma/rowsum[n] * (v @ P^T)
    mma_gemm<false, 0, 4><<<dim3(8, 4, BATCH), 256, SM_PLAIN>>>(
        p_vb, nullptr, p_P, nullptr, NTOK, NTOK, sO, sAt,
        out, NTOK, sO, p_rsum, gamma, NTOK);
}

// round 9
// speedup vs baseline: 6.2982x; 1.0024x over previous
#include <cuda_runtime.h>
#include <cuda_bf16.h>
#include <cstdint>
#include <cstddef>

#define HIDC 512
#define NTOK 1024
#define BATCH 32
#define CEFF 1280

typedef __nv_bfloat16 bf16;

// ------------------------- scratch ---------------------------------------
__device__ float g_bqc[HIDC];
__device__ float g_rsum[(size_t)BATCH * NTOK];

__device__ bf16 g_Wq_h[HIDC * HIDC], g_Wk_h[HIDC * HIDC], g_Wv_h[HIDC * HIDC];
__device__ bf16 g_We_h[HIDC * CEFF];
__device__ bf16 g_WcT[HIDC * HIDC];
__device__ bf16 g_Wc_h[HIDC * HIDC], g_Wc_l[HIDC * HIDC];
__device__ bf16 g_Wqc_h[HIDC * HIDC];

__device__ bf16 g_XcT_h[(size_t)BATCH * NTOK * HIDC];
__device__ bf16 g_XcT_l[(size_t)BATCH * NTOK * HIDC];
__device__ bf16 g_XeT_h[(size_t)BATCH * NTOK * CEFF];

__device__ bf16 g_eff[(size_t)BATCH * NTOK * HIDC];
__device__ bf16 g_qb[(size_t)BATCH * NTOK * HIDC];
__device__ bf16 g_kb[(size_t)BATCH * NTOK * HIDC];
__device__ bf16 g_vb[(size_t)BATCH * HIDC * NTOK];
__device__ bf16 g_P[(size_t)BATCH * NTOK * NTOK];

#define MMA_B16(D, A_, B_) \
    asm volatile("mma.sync.aligned.m16n8k16.row.col.f32.bf16.bf16.f32 " \
        "{%0,%1,%2,%3}, {%4,%5,%6,%7}, {%8,%9}, {%0,%1,%2,%3};" \
        : "+f"((D)[0]), "+f"((D)[1]), "+f"((D)[2]), "+f"((D)[3]) \
        : "r"((A_)[0]), "r"((A_)[1]), "r"((A_)[2]), "r"((A_)[3]), \
          "r"((B_)[0]), "r"((B_)[1]))

#define LDSM4(R0, R1, R2, R3, ADDR) \
    asm volatile("ldmatrix.sync.aligned.m8n8.x4.shared.b16 {%0,%1,%2,%3}, [%4];" \
        : "=r"(R0), "=r"(R1), "=r"(R2), "=r"(R3) : "r"(ADDR))

__device__ __forceinline__ uint32_t smem_u32(const void* p) {
    uint32_t a;
    asm("{ .reg .u64 t; cvta.to.shared.u64 t, %1; cvt.u32.u64 %0, t; }" : "=r"(a) : "l"(p));
    return a;
}
__device__ __forceinline__ void cp16(uint32_t dst, const void* src) {
    asm volatile("cp.async.cg.shared.global [%0], [%1], 16;" :: "r"(dst), "l"(src));
}
__device__ __forceinline__ void cp_commit() {
    asm volatile("cp.async.commit_group;" ::: "memory");
}
template<int N> __device__ __forceinline__ void cp_wait() {
    asm volatile("cp.async.wait_group %0;" :: "n"(N) : "memory");
}

#define TILEB 18432   // 128 rows * 72 elems * 2B

// inner compute on one stage buffer (plain, no split)
#define MAINLOOP_BODY(SBASE) \
    _Pragma("unroll") \
    for (int ks = 0; ks < 64; ks += 16) { \
        uint32_t a[4][4], bb[4][2]; \
        _Pragma("unroll") \
        for (int mt = 0; mt < 4; mt++) \
            LDSM4(a[mt][0], a[mt][1], a[mt][2], a[mt][3], \
                  (SBASE) + offA + mt * 2304 + ks * 2); \
        _Pragma("unroll") \
        for (int p = 0; p < 2; p++) \
            LDSM4(bb[2 * p][0], bb[2 * p][1], bb[2 * p + 1][0], bb[2 * p + 1][1], \
                  (SBASE) + TILEB + offB + p * 2304 + ks * 2); \
        _Pragma("unroll") \
        for (int mt = 0; mt < 4; mt++) \
            _Pragma("unroll") \
            for (int nt = 0; nt < 4; nt++) \
                MMA_B16(acc[mt][nt], a[mt], bb[nt]); \
    }

// ---------------------------------------------------------------------------
// bf16 HMMA GEMM, 3-stage cp.async pipeline, BK=64, ldmatrix fragments.
// C[M0+128, N0+128] = sum_K A[m,k] * B[n,k]  (both K-major)
// SPLIT adds Ah*Bl + Al*Bh.  BIASM: 0 none, 1 bias[row], 2 bias[col]
// OUTM: 0 fp32 row-major (+bias) | 1 bf16 row-major (+bias)
//       3 bf16 exp(D) + rowsum atomics | 4 fp32 RMW += gamma/rowsum[col]*D
// ---------------------------------------------------------------------------
template<bool SPLIT, int BIASM, int OUTM>
__global__ __launch_bounds__(256) void mma_gemm(
    const bf16* __restrict__ Ah, const bf16* __restrict__ Al,
    const bf16* __restrict__ Bh, const bf16* __restrict__ Bl,
    int lda, int ldb, size_t sA, size_t sB,
    void* __restrict__ Cout, int ldc, size_t sC,
    const float* __restrict__ bias, const float* __restrict__ gamma, int K)
{
    extern __shared__ char dynsm[];
    constexpr int STAGE = SPLIT ? 4 * TILEB : 2 * TILEB;
    const uint32_t sm0 = smem_u32(dynsm);

    const int tid = threadIdx.x;
    const int wid = tid >> 5;
    const int lid = tid & 31;
    const int wm = wid & 1;
    const int wn = wid >> 1;
    const int g  = lid >> 2;
    const int tc = (lid & 3) * 2;

    const int M0 = blockIdx.y * 128;
    const int N0 = blockIdx.x * 128;
    const int b  = blockIdx.z;

    const bf16* pA = Ah + (size_t)b * sA + (size_t)M0 * lda;
    const bf16* pB = Bh + (size_t)b * sB + (size_t)N0 * ldb;
    const bf16* pAl = SPLIT ? (Al + (size_t)b * sA + (size_t)M0 * lda) : nullptr;
    const bf16* pBl = SPLIT ? (Bl + (size_t)b * sB + (size_t)N0 * ldb) : nullptr;

    const int l8  = lid & 7;
    const int mi1 = (lid >> 3) & 1;
    const int mi2 = (lid >> 4) & 1;
    const uint32_t offA = (uint32_t)(((wm * 64 + mi1 * 8 + l8) * 72 + mi2 * 8) * 2);
    const uint32_t offB = (uint32_t)(((wn * 32 + mi2 * 8 + l8) * 72 + mi1 * 8) * 2);

    float acc[4][4][4];
    #pragma unroll
    for (int i = 0; i < 4; i++)
        #pragma unroll
        for (int j = 0; j < 4; j++)
            #pragma unroll
            for (int r = 0; r < 4; r++) acc[i][j][r] = 0.f;

    const int nk = K >> 6;

    auto copy_stage = [&](int buf, int kt) {
        const int k0 = kt << 6;
        const uint32_t sb = sm0 + buf * STAGE;
        #pragma unroll
        for (int s = 0; s < 4; s++) {
            const int i = tid + s * 256;
            const int r = i >> 3, c = (i & 7) * 8;
            const uint32_t so = (uint32_t)((r * 72 + c) * 2);
            cp16(sb + so,         pA + (size_t)r * lda + k0 + c);
            cp16(sb + TILEB + so, pB + (size_t)r * ldb + k0 + c);
            if (SPLIT) {
                cp16(sb + 2 * TILEB + so, pAl + (size_t)r * lda + k0 + c);
                cp16(sb + 3 * TILEB + so, pBl + (size_t)r * ldb + k0 + c);
            }
        }
        cp_commit();
    };

    copy_stage(0, 0);
    copy_stage(1, 1);          // nk >= 8 always here

    int buf = 0;
    for (int kt = 0; kt < nk; kt++) {
        if (kt + 2 < nk) {
            int nb = buf + 2; if (nb >= 3) nb -= 3;
            copy_stage(nb, kt + 2);
            cp_wait<2>();
        } else if (kt + 1 < nk) {
            cp_wait<1>();
        } else {
            cp_wait<0>();
        }
        __syncthreads();

        const uint32_t sb = sm0 + buf * STAGE;
        MAINLOOP_BODY(sb)
        if (SPLIT) {
            #pragma unroll
            for (int ks = 0; ks < 64; ks += 16) {
                uint32_t a[4][4], bb[4][2], al[4][4], bl[4][2];
                #pragma unroll
                for (int mt = 0; mt < 4; mt++) {
                    LDSM4(a[mt][0], a[mt][1], a[mt][2], a[mt][3],
                          sb + offA + mt * 2304 + ks * 2);
                    LDSM4(al[mt][0], al[mt][1], al[mt][2], al[mt][3],
                          sb + 2 * TILEB + offA + mt * 2304 + ks * 2);
                }
                #pragma unroll
                for (int p = 0; p < 2; p++) {
                    LDSM4(bb[2 * p][0], bb[2 * p][1], bb[2 * p + 1][0], bb[2 * p + 1][1],
                          sb + TILEB + offB + p * 2304 + ks * 2);
                    LDSM4(bl[2 * p][0], bl[2 * p][1], bl[2 * p + 1][0], bl[2 * p + 1][1],
                          sb + 3 * TILEB + offB + p * 2304 + ks * 2);
                }
                #pragma unroll
                for (int mt = 0; mt < 4; mt++)
                    #pragma unroll
                    for (int nt = 0; nt < 4; nt++) {
                        MMA_B16(acc[mt][nt], a[mt], bl[nt]);
                        MMA_B16(acc[mt][nt], al[mt], bb[nt]);
                    }
            }
        }
        __syncthreads();
        if (++buf == 3) buf = 0;
    }

    // ---------------- epilogue ----------------
    if (OUTM == 3) {
        __shared__ float srow[128];
        float* rs = const_cast<float*>(bias) + (size_t)b * NTOK;
        if (tid < 128) srow[tid] = 0.f;
        __syncthreads();
        bf16* C = (bf16*)Cout + (size_t)b * sC;
        #pragma unroll
        for (int mt = 0; mt < 4; mt++) {
            const int grow = M0 + wm * 64 + mt * 16 + g;
            float rp0 = 0.f, rp1 = 0.f;
            #pragma unroll
            for (int nt = 0; nt < 4; nt++) {
                const int gcol = N0 + wn * 32 + nt * 8 + tc;
                float e0 = __expf(acc[mt][nt][0]);
                float e1 = __expf(acc[mt][nt][1]);
                float e2 = __expf(acc[mt][nt][2]);
                float e3 = __expf(acc[mt][nt][3]);
                *(__nv_bfloat162*)(C + (size_t)grow * ldc + gcol) = __floats2bfloat162_rn(e0, e1);
                *(__nv_bfloat162*)(C + (size_t)(grow + 8) * ldc + gcol) = __floats2bfloat162_rn(e2, e3);
                rp0 += e0 + e1;
                rp1 += e2 + e3;
            }
            rp0 += __shfl_xor_sync(0xFFFFFFFFu, rp0, 1);
            rp0 += __shfl_xor_sync(0xFFFFFFFFu, rp0, 2);
            rp1 += __shfl_xor_sync(0xFFFFFFFFu, rp1, 1);
            rp1 += __shfl_xor_sync(0xFFFFFFFFu, rp1, 2);
            if ((lid & 3) == 0) {
                atomicAdd(&srow[wm * 64 + mt * 16 + g], rp0);
                atomicAdd(&srow[wm * 64 + mt * 16 + 8 + g], rp1);
            }
        }
        __syncthreads();
        if (tid < 128) atomicAdd(rs + M0 + tid, srow[tid]);
        return;
    }

    const float gm = (OUTM == 4) ? gamma[0] : 0.f;
    #pragma unroll
    for (int mt = 0; mt < 4; mt++) {
        #pragma unroll
        for (int nt = 0; nt < 4; nt++) {
            const int grow = M0 + wm * 64 + mt * 16 + g;
            const int gcol = N0 + wn * 32 + nt * 8 + tc;
            float d0 = acc[mt][nt][0], d1 = acc[mt][nt][1];
            float d2 = acc[mt][nt][2], d3 = acc[mt][nt][3];

            if (OUTM == 0) {
                float* C = (float*)Cout + (size_t)b * sC;
                if (BIASM == 1) {
                    float br0 = __ldg(bias + grow), br1 = __ldg(bias + grow + 8);
                    d0 += br0; d1 += br0; d2 += br1; d3 += br1;
                } else if (BIASM == 2) {
                    float bc0 = __ldg(bias + gcol), bc1 = __ldg(bias + gcol + 1);
                    d0 += bc0; d1 += bc1; d2 += bc0; d3 += bc1;
                }
                *(float2*)(C + (size_t)grow * ldc + gcol) = make_float2(d0, d1);
                *(float2*)(C + (size_t)(grow + 8) * ldc + gcol) = make_float2(d2, d3);
            } else if (OUTM == 1) {
                bf16* C = (bf16*)Cout + (size_t)b * sC;
                if (BIASM == 1) {
                    float br0 = __ldg(bias + grow), br1 = __ldg(bias + grow + 8);
                    d0 += br0; d1 += br0; d2 += br1; d3 += br1;
                } else if (BIASM == 2) {
                    float bc0 = __ldg(bias + gcol), bc1 = __ldg(bias + gcol + 1);
                    d0 += bc0; d1 += bc1; d2 += bc0; d3 += bc1;
                }
                *(__nv_bfloat162*)(C + (size_t)grow * ldc + gcol) = __floats2bfloat162_rn(d0, d1);
                *(__nv_bfloat162*)(C + (size_t)(grow + 8) * ldc + gcol) = __floats2bfloat162_rn(d2, d3);
            } else { // OUTM == 4
                const float* rs = bias + (size_t)b * NTOK;
                const float s0 = gm / __ldg(rs + gcol);
                const float s1 = gm / __ldg(rs + gcol + 1);
                float* C = (float*)Cout + (size_t)b * sC;
                float2 c0 = *(float2*)(C + (size_t)grow * ldc + gcol);
                float2 c1 = *(float2*)(C + (size_t)(grow + 8) * ldc + gcol);
                c0.x += s0 * d0; c0.y += s1 * d1;
                c1.x += s0 * d2; c1.y += s1 * d3;
                *(float2*)(C + (size_t)grow * ldc + gcol) = c0;
                *(float2*)(C + (size_t)(grow + 8) * ldc + gcol) = c1;
            }
        }
    }
}

// ---------------------------------------------------------------------------
// Dual GEMM: two independent OUTM=1/BIASM=2 GEMMs in one launch, selected by
// blockIdx.z (< zsplit -> desc 0, else desc 1). Same grid.xy shape for both.
// ---------------------------------------------------------------------------
struct GDesc {
    const bf16* A; const bf16* B;
    size_t sA, sB; int lda, ldb, K;
    bf16* C; int ldc; size_t sC;
    const float* bias;
};

__global__ __launch_bounds__(256) void mma_gemm_dual(GDesc d0, GDesc d1, int zsplit)
{
    extern __shared__ char dynsm[];
    constexpr int STAGE = 2 * TILEB;
    const uint32_t sm0 = smem_u32(dynsm);

    const int tid = threadIdx.x;
    const int wid = tid >> 5;
    const int lid = tid & 31;
    const int wm = wid & 1;
    const int wn = wid >> 1;
    const int g  = lid >> 2;
    const int tc = (lid & 3) * 2;

    const bool second = (int)blockIdx.z >= zsplit;
    const GDesc d = second ? d1 : d0;
    const int b = second ? (int)blockIdx.z - zsplit : (int)blockIdx.z;

    const int M0 = blockIdx.y * 128;
    const int N0 = blockIdx.x * 128;

    const bf16* pA = d.A + (size_t)b * d.sA + (size_t)M0 * d.lda;
    const bf16* pB = d.B + (size_t)b * d.sB + (size_t)N0 * d.ldb;

    const int l8  = lid & 7;
    const int mi1 = (lid >> 3) & 1;
    const int mi2 = (lid >> 4) & 1;
    const uint32_t offA = (uint32_t)(((wm * 64 + mi1 * 8 + l8) * 72 + mi2 * 8) * 2);
    const uint32_t offB = (uint32_t)(((wn * 32 + mi2 * 8 + l8) * 72 + mi1 * 8) * 2);

    float acc[4][4][4];
    #pragma unroll
    for (int i = 0; i < 4; i++)
        #pragma unroll
        for (int j = 0; j < 4; j++)
            #pragma unroll
            for (int r = 0; r < 4; r++) acc[i][j][r] = 0.f;

    const int nk = d.K >> 6;

    auto copy_stage = [&](int buf, int kt) {
        const int k0 = kt << 6;
        const uint32_t sb = sm0 + buf * STAGE;
        #pragma unroll
        for (int s = 0; s < 4; s++) {
            const int i = tid + s * 256;
            const int r = i >> 3, c = (i & 7) * 8;
            const uint32_t so = (uint32_t)((r * 72 + c) * 2);
            cp16(sb + so,         pA + (size_t)r * d.lda + k0 + c);
            cp16(sb + TILEB + so, pB + (size_t)r * d.ldb + k0 + c);
        }
        cp_commit();
    };

    copy_stage(0, 0);
    copy_stage(1, 1);

    int buf = 0;
    for (int kt = 0; kt < nk; kt++) {
        if (kt + 2 < nk) {
            int nb = buf + 2; if (nb >= 3) nb -= 3;
            copy_stage(nb, kt + 2);
            cp_wait<2>();
        } else if (kt + 1 < nk) {
            cp_wait<1>();
        } else {
            cp_wait<0>();
        }
        __syncthreads();
        const uint32_t sb = sm0 + buf * STAGE;
        MAINLOOP_BODY(sb)
        __syncthreads();
        if (++buf == 3) buf = 0;
    }

    #pragma unroll
    for (int mt = 0; mt < 4; mt++) {
        #pragma unroll
        for (int nt = 0; nt < 4; nt++) {
            const int grow = M0 + wm * 64 + mt * 16 + g;
            const int gcol = N0 + wn * 32 + nt * 8 + tc;
            float bc0 = __ldg(d.bias + gcol), bc1 = __ldg(d.bias + gcol + 1);
            bf16* C = d.C + (size_t)b * d.sC;
            *(__nv_bfloat162*)(C + (size_t)grow * d.ldc + gcol) =
                __floats2bfloat162_rn(acc[mt][nt][0] + bc0, acc[mt][nt][1] + bc1);
            *(__nv_bfloat162*)(C + (size_t)(grow + 8) * d.ldc + gcol) =
                __floats2bfloat162_rn(acc[mt][nt][2] + bc0, acc[mt][nt][3] + bc1);
        }
    }
}

// transpose fp32 [b][C][1024] -> bf16 hi(/lo) [b][1024][C]
__global__ __launch_bounds__(256) void transpose_split(
    const float* __restrict__ in, bf16* __restrict__ hi, bf16* __restrict__ lo, int C)
{
    __shared__ float t[32][33];
    const int c0 = blockIdx.x * 32, n0 = blockIdx.y * 32, b = blockIdx.z;
    const float* pin = in + (size_t)b * C * NTOK;
    const int tx = threadIdx.x & 31, ty = threadIdx.x >> 5;
    #pragma unroll
    for (int i = 0; i < 4; i++)
        t[ty + i * 8][tx] = pin[(size_t)(c0 + ty + i * 8) * NTOK + n0 + tx];
    __syncthreads();
    #pragma unroll
    for (int i = 0; i < 4; i++) {
        float x = t[tx][ty + i * 8];
        bf16 h = __float2bfloat16(x);
        size_t o = (size_t)b * NTOK * C + (size_t)(n0 + ty + i * 8) * C + c0 + tx;
        hi[o] = h;
        if (lo) lo[o] = __float2bfloat16(x - __bfloat162float(h));
    }
}

__global__ __launch_bounds__(256) void transpose_wc(
    const float* __restrict__ Wc, bf16* __restrict__ WcT)
{
    __shared__ float t[32][33];
    const int c0 = blockIdx.x * 32, r0 = blockIdx.y * 32;
    const int tx = threadIdx.x & 31, ty = threadIdx.x >> 5;
    #pragma unroll
    for (int i = 0; i < 4; i++)
        t[ty + i * 8][tx] = Wc[(size_t)(r0 + ty + i * 8) * HIDC + c0 + tx];
    __syncthreads();
    #pragma unroll
    for (int i = 0; i < 4; i++)
        WcT[(size_t)(c0 + ty + i * 8) * HIDC + r0 + tx] = __float2bfloat16(t[tx][ty + i * 8]);
}

__global__ void cast_weights(
    const float* __restrict__ Wq, const float* __restrict__ Wk,
    const float* __restrict__ Wv, const float* __restrict__ Wc,
    const float* __restrict__ We,
    bf16* __restrict__ oq, bf16* __restrict__ ok, bf16* __restrict__ ov,
    bf16* __restrict__ ch, bf16* __restrict__ cl, bf16* __restrict__ oe)
{
    const int i = blockIdx.x * 256 + threadIdx.x;
    const int w = blockIdx.y;
    if (w == 4) {
        if (i < HIDC * CEFF) oe[i] = __float2bfloat16(We[i]);
        return;
    }
    if (i >= HIDC * HIDC) return;
    if (w == 0)      oq[i] = __float2bfloat16(Wq[i]);
    else if (w == 1) ok[i] = __float2bfloat16(Wk[i]);
    else if (w == 2) ov[i] = __float2bfloat16(Wv[i]);
    else {
        float x = Wc[i];
        bf16 h = __float2bfloat16(x);
        ch[i] = h;
        cl[i] = __float2bfloat16(x - __bfloat162float(h));
    }
}

__global__ void combine_qbias(
    const float* __restrict__ Wq, const float* __restrict__ bcnn,
    const float* __restrict__ bq, float* __restrict__ bqc)
{
    const int o = blockIdx.x * 8 + (threadIdx.x >> 5);
    const int l = threadIdx.x & 31;
    float s = 0.f;
    for (int c = l; c < HIDC; c += 32) s += Wq[(size_t)o * HIDC + c] * bcnn[c];
    #pragma unroll
    for (int d = 16; d; d >>= 1) s += __shfl_xor_sync(0xFFFFFFFFu, s, d);
    if (l == 0) bqc[o] = s + bq[o];
}

// ------------------------------ launch ------------------------------------
extern "C" void kernel_launch(void* const* d_in, const int* in_sizes, int n_in,
                              void* d_out, int out_size)
{
    const float* xc = (const float*)d_in[0];
    const float* xe = (const float*)d_in[1];
    const float* Wc = (const float*)d_in[2];
    const float* bc = (const float*)d_in[3];
    const float* We = (const float*)d_in[4];
    const float* be = (const float*)d_in[5];
    const float* Wq = (const float*)d_in[6];
    const float* bq = (const float*)d_in[7];
    const float* Wk = (const float*)d_in[8];
    const float* bk = (const float*)d_in[9];
    const float* Wv = (const float*)d_in[10];
    const float* bv = (const float*)d_in[11];
    const float* gamma = (const float*)d_in[12];
    float* out = (float*)d_out;

    float *p_bqc, *p_rsum;
    bf16 *p_Wq_h, *p_Wk_h, *p_Wv_h, *p_We_h, *p_WcT, *p_Wc_h, *p_Wc_l, *p_Wqc_h;
    bf16 *p_XcT_h, *p_XcT_l, *p_XeT_h, *p_eff, *p_qb, *p_kb, *p_vb, *p_P;
    cudaGetSymbolAddress((void**)&p_bqc, g_bqc);
    cudaGetSymbolAddress((void**)&p_rsum, g_rsum);
    cudaGetSymbolAddress((void**)&p_Wq_h, g_Wq_h);
    cudaGetSymbolAddress((void**)&p_Wk_h, g_Wk_h);
    cudaGetSymbolAddress((void**)&p_Wv_h, g_Wv_h);
    cudaGetSymbolAddress((void**)&p_We_h, g_We_h);
    cudaGetSymbolAddress((void**)&p_WcT, g_WcT);
    cudaGetSymbolAddress((void**)&p_Wc_h, g_Wc_h);
    cudaGetSymbolAddress((void**)&p_Wc_l, g_Wc_l);
    cudaGetSymbolAddress((void**)&p_Wqc_h, g_Wqc_h);
    cudaGetSymbolAddress((void**)&p_XcT_h, g_XcT_h);
    cudaGetSymbolAddress((void**)&p_XcT_l, g_XcT_l);
    cudaGetSymbolAddress((void**)&p_XeT_h, g_XeT_h);
    cudaGetSymbolAddress((void**)&p_eff, g_eff);
    cudaGetSymbolAddress((void**)&p_qb, g_qb);
    cudaGetSymbolAddress((void**)&p_kb, g_kb);
    cudaGetSymbolAddress((void**)&p_vb, g_vb);
    cudaGetSymbolAddress((void**)&p_P, g_P);

    const int SM_PLAIN = 3 * 2 * TILEB;   // 110592
    const int SM_SPLIT = 3 * 4 * TILEB;   // 221184
    cudaFuncSetAttribute(mma_gemm<true, 1, 0>, cudaFuncAttributeMaxDynamicSharedMemorySize, SM_SPLIT);
    cudaFuncSetAttribute(mma_gemm<false, 0, 1>, cudaFuncAttributeMaxDynamicSharedMemorySize, SM_PLAIN);
    cudaFuncSetAttribute(mma_gemm<false, 2, 1>, cudaFuncAttributeMaxDynamicSharedMemorySize, SM_PLAIN);
    cudaFuncSetAttribute(mma_gemm<false, 1, 1>, cudaFuncAttributeMaxDynamicSharedMemorySize, SM_PLAIN);
    cudaFuncSetAttribute(mma_gemm<false, 0, 3>, cudaFuncAttributeMaxDynamicSharedMemorySize, SM_PLAIN);
    cudaFuncSetAttribute(mma_gemm<false, 0, 4>, cudaFuncAttributeMaxDynamicSharedMemorySize, SM_PLAIN);
    cudaFuncSetAttribute(mma_gemm_dual, cudaFuncAttributeMaxDynamicSharedMemorySize, SM_PLAIN);

    const size_t sXc = (size_t)NTOK * HIDC;
    const size_t sXe = (size_t)NTOK * CEFF;
    const size_t sO  = (size_t)HIDC * NTOK;
    const size_t sAt = (size_t)NTOK * NTOK;

    // prep
    cast_weights<<<dim3(2560, 5), 256>>>(Wq, Wk, Wv, Wc, We,
        p_Wq_h, p_Wk_h, p_Wv_h, p_Wc_h, p_Wc_l, p_We_h);
    transpose_wc<<<dim3(16, 16), 256>>>(Wc, p_WcT);
    combine_qbias<<<64, 256>>>(Wq, bc, bq, p_bqc);

    // fold Wqc = Wq @ Wc
    mma_gemm<false, 0, 1><<<dim3(4, 4, 1), 256, SM_PLAIN>>>(
        p_Wq_h, nullptr, p_WcT, nullptr, HIDC, HIDC, 0, 0,
        p_Wqc_h, HIDC, 0, nullptr, nullptr, HIDC);

    // activation transposes
    transpose_split<<<dim3(16, 32, BATCH), 256>>>(xc, p_XcT_h, p_XcT_l, HIDC);
    transpose_split<<<dim3(40, 32, BATCH), 256>>>(xe, p_XeT_h, nullptr, CEFF);

    // cnn_proj (split bf16) -> d_out fp32 [b][c][n]
    mma_gemm<true, 1, 0><<<dim3(8, 4, BATCH), 256, SM_SPLIT>>>(
        p_Wc_h, p_Wc_l, p_XcT_h, p_XcT_l, HIDC, HIDC, 0, sXc,
        out, NTOK, sO, bc, nullptr, HIDC);

    // q + eff merged (both OUTM=1/BIASM=2, grid xy (4,8))
    {
        GDesc dq = { p_XcT_h, p_Wqc_h, sXc, 0, HIDC, HIDC, HIDC,
                     p_qb, HIDC, sXc, p_bqc };
        GDesc de = { p_XeT_h, p_We_h, sXe, 0, CEFF, CEFF, CEFF,
                     p_eff, HIDC, sXc, be };
        mma_gemm_dual<<<dim3(4, 8, 2 * BATCH), 256, SM_PLAIN>>>(dq, de, BATCH);
    }

    // k[b][m][c] = eff @ Wk^T + bk
    mma_gemm<false, 2, 1><<<dim3(4, 8, BATCH), 256, SM_PLAIN>>>(
        p_eff, nullptr, p_Wk_h, nullptr, HIDC, HIDC, sXc, 0,
        p_kb, HIDC, sXc, bk, nullptr, HIDC);

    // v[b][c][m] = Wv @ eff^T + bv
    mma_gemm<false, 1, 1><<<dim3(8, 4, BATCH), 256, SM_PLAIN>>>(
        p_Wv_h, nullptr, p_eff, nullptr, HIDC, HIDC, 0, sXc,
        p_vb, NTOK, sO, bv, nullptr, HIDC);

    // fused logits + exp + rowsum -> P (unnormalized)
    cudaMemsetAsync(p_rsum, 0, (size_t)BATCH * NTOK * sizeof(float));
    mma_gemm<false, 0, 3><<<dim3(8, 8, BATCH), 256, SM_PLAIN>>>(
        p_qb, nullptr, p_kb, nullptr, HIDC, HIDC, sXc, sXc,
        p_P, NTOK, sAt, p_rsum, nullptr, HIDC);

    // out[b][c][n] += gamma/rowsum[n] * (v @ P^T)
    mma_gemm<false, 0, 4><<<dim3(8, 4, BATCH), 256, SM_PLAIN>>>(
        p_vb, nullptr, p_P, nullptr, NTOK, NTOK, sO, sAt,
        out, NTOK, sO, p_rsum, gamma, NTOK);
}